// round 2
// baseline (speedup 1.0000x reference)
#include <cuda_runtime.h>
#include <math.h>

#define BT     4096      // B*T
#define DMODEL 1024
#define QKVN   3072
#define HEADS  16
#define DHEAD  64
#define TSEQ   2048
#define NBATCH 2

// Scratch (allocation-free rule: __device__ globals)
__device__ float g_qkv[(size_t)BT * QKVN];   // [B*T, 3D]
__device__ float g_attn[(size_t)BT * DMODEL];// [B*T, D]

// ---------------------------------------------------------------------------
// C[M,N] = A[M,K] * B[N,K]^T   (row-major, all dims multiples of 128 / K of 8)
// 128x128 block tile, BK=8, 256 threads, 8x8 microtile per thread.
// ---------------------------------------------------------------------------
__global__ __launch_bounds__(256) void sgemm_nt(
    const float* __restrict__ A, const float* __restrict__ B,
    float* __restrict__ C, int M, int N, int K)
{
    __shared__ float As[8][128];
    __shared__ float Bs[8][128];

    const int tid = threadIdx.x;
    const int tx  = tid & 15;
    const int ty  = tid >> 4;
    const int bn  = blockIdx.x;
    const int bm  = blockIdx.y;

    const float* Ag = A + (size_t)bm * 128 * K;
    const float* Bg = B + (size_t)bn * 128 * K;

    const int lr = tid >> 1;        // 0..127 (tile row loaded by this thread)
    const int lc = (tid & 1) << 2;  // 0 or 4 (float4 column offset within BK=8)

    float acc[8][8];
#pragma unroll
    for (int i = 0; i < 8; ++i)
#pragma unroll
        for (int j = 0; j < 8; ++j) acc[i][j] = 0.f;

    for (int k0 = 0; k0 < K; k0 += 8) {
        float4 av = *(const float4*)(Ag + (size_t)lr * K + k0 + lc);
        float4 bv = *(const float4*)(Bg + (size_t)lr * K + k0 + lc);
        As[lc + 0][lr] = av.x; As[lc + 1][lr] = av.y;
        As[lc + 2][lr] = av.z; As[lc + 3][lr] = av.w;
        Bs[lc + 0][lr] = bv.x; Bs[lc + 1][lr] = bv.y;
        Bs[lc + 2][lr] = bv.z; Bs[lc + 3][lr] = bv.w;
        __syncthreads();
#pragma unroll
        for (int kk = 0; kk < 8; ++kk) {
            float a[8], b[8];
            *(float4*)(a)     = *(const float4*)&As[kk][ty * 8];
            *(float4*)(a + 4) = *(const float4*)&As[kk][ty * 8 + 4];
            *(float4*)(b)     = *(const float4*)&Bs[kk][tx * 8];
            *(float4*)(b + 4) = *(const float4*)&Bs[kk][tx * 8 + 4];
#pragma unroll
            for (int i = 0; i < 8; ++i)
#pragma unroll
                for (int j = 0; j < 8; ++j)
                    acc[i][j] = fmaf(a[i], b[j], acc[i][j]);
        }
        __syncthreads();
    }

#pragma unroll
    for (int i = 0; i < 8; ++i) {
        float* Crow = C + (size_t)(bm * 128 + ty * 8 + i) * N + bn * 128 + tx * 8;
        *(float4*)(Crow)     = make_float4(acc[i][0], acc[i][1], acc[i][2], acc[i][3]);
        *(float4*)(Crow + 4) = make_float4(acc[i][4], acc[i][5], acc[i][6], acc[i][7]);
    }
}

// ---------------------------------------------------------------------------
// Flash-style attention. One block per (b, h, 64-query tile).
// 256 threads (16x16), each owns a 4x4 microtile of the 64x64 S/O tiles.
// K and V share one smem buffer; P goes through smem for the PV GEMM.
// Dynamic smem: 3 * 64 * 65 floats = 49920 bytes.
// ---------------------------------------------------------------------------
#define ATTN_SMEM (3 * 64 * 65 * 4)

__global__ __launch_bounds__(256) void attn_kernel(float* __restrict__ out)
{
    extern __shared__ float sm[];
    float* Qs  = sm;               // [64][65], pre-scaled by 1/8
    float* KVs = sm + 64 * 65;     // [64][65], holds K then V per tile
    float* Ps  = sm + 2 * 64 * 65; // [64][65]

    const int qt  = blockIdx.x;
    const int h   = blockIdx.y;
    const int b   = blockIdx.z;
    const int tid = threadIdx.x;
    const int tx  = tid & 15;
    const int ty  = tid >> 4;

    const size_t base = (size_t)b * TSEQ * QKVN;
    const int lr = tid >> 2;        // 0..63 row
    const int lc = (tid & 3) * 16;  // 16-float segment of the 64-wide row

    // Load Q tile, folding in 1/sqrt(dh) = 0.125
    {
        const float* gq = g_qkv + base + (size_t)(qt * 64 + lr) * QKVN + h * DHEAD + lc;
#pragma unroll
        for (int u = 0; u < 4; ++u) {
            float4 v = *(const float4*)(gq + u * 4);
            float* d = &Qs[lr * 65 + lc + u * 4];
            d[0] = v.x * 0.125f; d[1] = v.y * 0.125f;
            d[2] = v.z * 0.125f; d[3] = v.w * 0.125f;
        }
    }

    float m_i[4], l_i[4], o[4][4];
#pragma unroll
    for (int i = 0; i < 4; ++i) {
        m_i[i] = -INFINITY;
        l_i[i] = 0.f;
#pragma unroll
        for (int j = 0; j < 4; ++j) o[i][j] = 0.f;
    }

    for (int kt = 0; kt < TSEQ / 64; ++kt) {
        __syncthreads();  // prior iter done reading KVs (and covers Q store on iter 0)
        // Load K tile
        {
            const float* gk = g_qkv + base + (size_t)(kt * 64 + lr) * QKVN
                            + DMODEL + h * DHEAD + lc;
#pragma unroll
            for (int u = 0; u < 4; ++u) {
                float4 v = *(const float4*)(gk + u * 4);
                float* d = &KVs[lr * 65 + lc + u * 4];
                d[0] = v.x; d[1] = v.y; d[2] = v.z; d[3] = v.w;
            }
        }
        __syncthreads();

        // S = Q * K^T  (64x64x64)
        float s[4][4];
#pragma unroll
        for (int i = 0; i < 4; ++i)
#pragma unroll
            for (int j = 0; j < 4; ++j) s[i][j] = 0.f;

#pragma unroll 4
        for (int d = 0; d < DHEAD; ++d) {
            float qv[4], kv[4];
#pragma unroll
            for (int i = 0; i < 4; ++i) qv[i] = Qs[(ty * 4 + i) * 65 + d];
#pragma unroll
            for (int j = 0; j < 4; ++j) kv[j] = KVs[(tx * 4 + j) * 65 + d];
#pragma unroll
            for (int i = 0; i < 4; ++i)
#pragma unroll
                for (int j = 0; j < 4; ++j)
                    s[i][j] = fmaf(qv[i], kv[j], s[i][j]);
        }

        // Online softmax (16-lane shuffle reductions across tx)
#pragma unroll
        for (int i = 0; i < 4; ++i) {
            float rm = fmaxf(fmaxf(s[i][0], s[i][1]), fmaxf(s[i][2], s[i][3]));
#pragma unroll
            for (int off = 8; off > 0; off >>= 1)
                rm = fmaxf(rm, __shfl_xor_sync(0xffffffffu, rm, off, 16));
            float mnew = fmaxf(m_i[i], rm);
            float e = __expf(m_i[i] - mnew);
            m_i[i] = mnew;
            float rs = 0.f;
#pragma unroll
            for (int j = 0; j < 4; ++j) {
                float p = __expf(s[i][j] - mnew);
                s[i][j] = p;
                rs += p;
            }
#pragma unroll
            for (int off = 8; off > 0; off >>= 1)
                rs += __shfl_xor_sync(0xffffffffu, rs, off, 16);
            l_i[i] = l_i[i] * e + rs;
#pragma unroll
            for (int j = 0; j < 4; ++j) o[i][j] *= e;
        }

        // Stage P
#pragma unroll
        for (int i = 0; i < 4; ++i)
#pragma unroll
            for (int j = 0; j < 4; ++j)
                Ps[(ty * 4 + i) * 65 + tx * 4 + j] = s[i][j];
        __syncthreads();  // everyone done reading K + P visible

        // Load V tile into the same buffer
        {
            const float* gv = g_qkv + base + (size_t)(kt * 64 + lr) * QKVN
                            + 2 * DMODEL + h * DHEAD + lc;
#pragma unroll
            for (int u = 0; u < 4; ++u) {
                float4 v = *(const float4*)(gv + u * 4);
                float* d = &KVs[lr * 65 + lc + u * 4];
                d[0] = v.x; d[1] = v.y; d[2] = v.z; d[3] = v.w;
            }
        }
        __syncthreads();

        // O += P * V  (64x64x64)
#pragma unroll 4
        for (int k = 0; k < 64; ++k) {
            float pv[4], vv[4];
#pragma unroll
            for (int i = 0; i < 4; ++i) pv[i] = Ps[(ty * 4 + i) * 65 + k];
#pragma unroll
            for (int j = 0; j < 4; ++j) vv[j] = KVs[k * 65 + tx * 4 + j];
#pragma unroll
            for (int i = 0; i < 4; ++i)
#pragma unroll
                for (int j = 0; j < 4; ++j)
                    o[i][j] = fmaf(pv[i], vv[j], o[i][j]);
        }
    }

    // Epilogue: normalize and write to g_attn layout [B*T, D]
#pragma unroll
    for (int i = 0; i < 4; ++i) {
        float inv = 1.f / l_i[i];
        float* op = out + ((size_t)b * TSEQ + qt * 64 + ty * 4 + i) * DMODEL
                        + h * DHEAD + tx * 4;
#pragma unroll
        for (int j = 0; j < 4; ++j) op[j] = o[i][j] * inv;
    }
}

// ---------------------------------------------------------------------------
extern "C" void kernel_launch(void* const* d_in, const int* in_sizes, int n_in,
                              void* d_out, int out_size)
{
    const float* x      = (const float*)d_in[0];   // [2,2048,1024]
    const float* w_qkv  = (const float*)d_in[1];   // [3072,1024]
    const float* w_proj = (const float*)d_in[2];   // [1024,1024]
    float* out = (float*)d_out;                    // [2,2048,1024]

    float *qkv = nullptr, *attn = nullptr;
    cudaGetSymbolAddress((void**)&qkv, g_qkv);
    cudaGetSymbolAddress((void**)&attn, g_attn);

    cudaFuncSetAttribute(attn_kernel,
                         cudaFuncAttributeMaxDynamicSharedMemorySize, ATTN_SMEM);

    // 1) QKV projection: [4096,3072] = x[4096,1024] @ w_qkv[3072,1024]^T
    dim3 g1(QKVN / 128, BT / 128);
    sgemm_nt<<<g1, 256>>>(x, w_qkv, qkv, BT, QKVN, DMODEL);

    // 2) Attention per (b, h, q-tile)
    dim3 ga(TSEQ / 64, HEADS, NBATCH);
    attn_kernel<<<ga, 256, ATTN_SMEM>>>(attn);

    // 3) Output projection: [4096,1024] = attn @ w_proj[1024,1024]^T
    dim3 g2(DMODEL / 128, BT / 128);
    sgemm_nt<<<g2, 256>>>(attn, w_proj, out, BT, DMODEL, DMODEL);
}

// round 5
// speedup vs baseline: 1.4325x; 1.4325x over previous
#include <cuda_runtime.h>
#include <math.h>
#include <stdint.h>

#define BT     4096      // B*T
#define DMODEL 1024
#define QKVN   3072
#define HEADS  16
#define DHEAD  64
#define TSEQ   2048
#define NBATCH 2

// Scratch (allocation-free rule: __device__ globals)
__device__ float g_qkv [(size_t)BT * QKVN];      // [B*T, 3D]
__device__ float g_attn[(size_t)BT * DMODEL];    // [B*T, D] (tf32-rounded)
__device__ float g_xr  [(size_t)BT * DMODEL];    // tf32-rounded x
__device__ float g_wqr [(size_t)QKVN * DMODEL];  // tf32-rounded w_qkv
__device__ float g_wpr [(size_t)DMODEL * DMODEL];// tf32-rounded w_proj

__device__ __forceinline__ uint32_t smem_u32(const void* p) {
    uint32_t a;
    asm("{ .reg .u64 t; cvta.to.shared.u64 t, %1; cvt.u32.u64 %0, t; }"
        : "=r"(a) : "l"(p));
    return a;
}
__device__ __forceinline__ float round_tf32(float x) {
    uint32_t t;
    asm("cvt.rna.tf32.f32 %0, %1;" : "=r"(t) : "f"(x));
    return __uint_as_float(t);
}

// mma.sync m16n8k8 tf32: D += A*B  (A 16x8 row-major, B 8x8 col-major)
__device__ __forceinline__ void mma_tf32(float* d, const uint32_t* a, const uint32_t* b) {
    asm volatile(
        "mma.sync.aligned.m16n8k8.row.col.f32.tf32.tf32.f32 "
        "{%0,%1,%2,%3}, {%4,%5,%6,%7}, {%8,%9}, {%0,%1,%2,%3};"
        : "+f"(d[0]), "+f"(d[1]), "+f"(d[2]), "+f"(d[3])
        : "r"(a[0]), "r"(a[1]), "r"(a[2]), "r"(a[3]), "r"(b[0]), "r"(b[1]));
}

// ---------------------------------------------------------------------------
// C[M,N] = A[M,K] * B[N,K]^T via mma.sync tf32.
// 128x128 CTA tile, BK=16, 2-stage cp.async double buffer.
// 8 warps in 2(m) x 4(n); warp tile 64x32 = 4x4 m16n8k8 fragments.
// smem: 2 stages * (A[128][20] + B[128][20]) floats = 40960 B (static).
// ---------------------------------------------------------------------------
__global__ __launch_bounds__(256, 2) void gemm_mma(
    const float* __restrict__ A, const float* __restrict__ B,
    float* __restrict__ C, int M, int N, int K)
{
    __shared__ float As[2][128][20];
    __shared__ float Bs[2][128][20];

    const int tid  = threadIdx.x;
    const int lane = tid & 31;
    const int wid  = tid >> 5;
    const int wm   = wid >> 2;       // 0..1
    const int wn   = wid & 3;        // 0..3
    const int bn   = blockIdx.x;
    const int bm   = blockIdx.y;
    const int KT   = K >> 4;

    const float* Ag = A + (size_t)bm * 128 * K;
    const float* Bg = B + (size_t)bn * 128 * K;

    float acc[4][4][4];
#pragma unroll
    for (int mi = 0; mi < 4; ++mi)
#pragma unroll
        for (int ni = 0; ni < 4; ++ni)
#pragma unroll
            for (int r = 0; r < 4; ++r) acc[mi][ni][r] = 0.f;

    // cp.async fill of one stage (kt-th 128x16 chunk of A and B)
    auto fill = [&](int kt) {
        const int st = kt & 1;
        const int k0 = kt << 4;
#pragma unroll
        for (int u = 0; u < 2; ++u) {
            int f   = u * 256 + tid;       // 0..511
            int row = f >> 2;
            int col = (f & 3) << 2;
            uint32_t da = smem_u32(&As[st][row][col]);
            uint32_t db = smem_u32(&Bs[st][row][col]);
            const float* sa = Ag + (size_t)row * K + k0 + col;
            const float* sb = Bg + (size_t)row * K + k0 + col;
            asm volatile("cp.async.cg.shared.global [%0], [%1], 16;" :: "r"(da), "l"(sa));
            asm volatile("cp.async.cg.shared.global [%0], [%1], 16;" :: "r"(db), "l"(sb));
        }
        asm volatile("cp.async.commit_group;" ::: "memory");
    };

    fill(0);

    const int lr = lane >> 2;   // 0..7
    const int lc = lane & 3;    // 0..3

    for (int kt = 0; kt < KT; ++kt) {
        if (kt + 1 < KT) {
            fill(kt + 1);
            asm volatile("cp.async.wait_group 1;" ::: "memory");
        } else {
            asm volatile("cp.async.wait_group 0;" ::: "memory");
        }
        __syncthreads();

        const int st = kt & 1;
#pragma unroll
        for (int ks = 0; ks < 16; ks += 8) {
            uint32_t af[4][4], bf[4][2];
#pragma unroll
            for (int mi = 0; mi < 4; ++mi) {
                const int r0 = wm * 64 + mi * 16 + lr;
                af[mi][0] = __float_as_uint(As[st][r0    ][ks + lc]);
                af[mi][1] = __float_as_uint(As[st][r0 + 8][ks + lc]);
                af[mi][2] = __float_as_uint(As[st][r0    ][ks + 4 + lc]);
                af[mi][3] = __float_as_uint(As[st][r0 + 8][ks + 4 + lc]);
            }
#pragma unroll
            for (int ni = 0; ni < 4; ++ni) {
                const int n0 = wn * 32 + ni * 8 + lr;
                bf[ni][0] = __float_as_uint(Bs[st][n0][ks + lc]);
                bf[ni][1] = __float_as_uint(Bs[st][n0][ks + 4 + lc]);
            }
#pragma unroll
            for (int mi = 0; mi < 4; ++mi)
#pragma unroll
                for (int ni = 0; ni < 4; ++ni)
                    mma_tf32(acc[mi][ni], af[mi], bf[ni]);
        }
        __syncthreads();
    }

    // Epilogue: write 64x32 warp tile
#pragma unroll
    for (int mi = 0; mi < 4; ++mi) {
#pragma unroll
        for (int ni = 0; ni < 4; ++ni) {
            const int r0 = bm * 128 + wm * 64 + mi * 16 + lr;
            const int c0 = bn * 128 + wn * 32 + ni * 8 + lc * 2;
            *(float2*)(C + (size_t)r0 * N + c0) =
                make_float2(acc[mi][ni][0], acc[mi][ni][1]);
            *(float2*)(C + (size_t)(r0 + 8) * N + c0) =
                make_float2(acc[mi][ni][2], acc[mi][ni][3]);
        }
    }
}

// ---------------------------------------------------------------------------
// Elementwise tf32 rounding (rna) — unbiased pre-rounding of GEMM operands.
// ---------------------------------------------------------------------------
__global__ __launch_bounds__(256) void round_tf32_kernel(
    const float* __restrict__ in, float* __restrict__ out, int n4)
{
    int i = blockIdx.x * blockDim.x + threadIdx.x;
    if (i < n4) {
        float4 v = ((const float4*)in)[i];
        v.x = round_tf32(v.x); v.y = round_tf32(v.y);
        v.z = round_tf32(v.z); v.w = round_tf32(v.w);
        ((float4*)out)[i] = v;
    }
}

// ---------------------------------------------------------------------------
// Flash-style attention (fp32 SIMT; epilogue emits tf32-rounded values).
// ---------------------------------------------------------------------------
#define ATTN_SMEM (3 * 64 * 65 * 4)

__global__ __launch_bounds__(256) void attn_kernel(float* __restrict__ out)
{
    extern __shared__ float sm[];
    float* Qs  = sm;               // [64][65], pre-scaled by 1/8
    float* KVs = sm + 64 * 65;     // [64][65]
    float* Ps  = sm + 2 * 64 * 65; // [64][65]

    const int qt  = blockIdx.x;
    const int h   = blockIdx.y;
    const int b   = blockIdx.z;
    const int tid = threadIdx.x;
    const int tx  = tid & 15;
    const int ty  = tid >> 4;

    const size_t base = (size_t)b * TSEQ * QKVN;
    const int lr = tid >> 2;
    const int lc = (tid & 3) * 16;

    {
        const float* gq = g_qkv + base + (size_t)(qt * 64 + lr) * QKVN + h * DHEAD + lc;
#pragma unroll
        for (int u = 0; u < 4; ++u) {
            float4 v = *(const float4*)(gq + u * 4);
            float* d = &Qs[lr * 65 + lc + u * 4];
            d[0] = v.x * 0.125f; d[1] = v.y * 0.125f;
            d[2] = v.z * 0.125f; d[3] = v.w * 0.125f;
        }
    }

    float m_i[4], l_i[4], o[4][4];
#pragma unroll
    for (int i = 0; i < 4; ++i) {
        m_i[i] = -INFINITY; l_i[i] = 0.f;
#pragma unroll
        for (int j = 0; j < 4; ++j) o[i][j] = 0.f;
    }

    for (int kt = 0; kt < TSEQ / 64; ++kt) {
        __syncthreads();
        {
            const float* gk = g_qkv + base + (size_t)(kt * 64 + lr) * QKVN
                            + DMODEL + h * DHEAD + lc;
#pragma unroll
            for (int u = 0; u < 4; ++u) {
                float4 v = *(const float4*)(gk + u * 4);
                float* d = &KVs[lr * 65 + lc + u * 4];
                d[0] = v.x; d[1] = v.y; d[2] = v.z; d[3] = v.w;
            }
        }
        __syncthreads();

        float s[4][4];
#pragma unroll
        for (int i = 0; i < 4; ++i)
#pragma unroll
            for (int j = 0; j < 4; ++j) s[i][j] = 0.f;

#pragma unroll 4
        for (int d = 0; d < DHEAD; ++d) {
            float qv[4], kv[4];
#pragma unroll
            for (int i = 0; i < 4; ++i) qv[i] = Qs[(ty * 4 + i) * 65 + d];
#pragma unroll
            for (int j = 0; j < 4; ++j) kv[j] = KVs[(tx * 4 + j) * 65 + d];
#pragma unroll
            for (int i = 0; i < 4; ++i)
#pragma unroll
                for (int j = 0; j < 4; ++j)
                    s[i][j] = fmaf(qv[i], kv[j], s[i][j]);
        }

#pragma unroll
        for (int i = 0; i < 4; ++i) {
            float rm = fmaxf(fmaxf(s[i][0], s[i][1]), fmaxf(s[i][2], s[i][3]));
#pragma unroll
            for (int off = 8; off > 0; off >>= 1)
                rm = fmaxf(rm, __shfl_xor_sync(0xffffffffu, rm, off, 16));
            float mnew = fmaxf(m_i[i], rm);
            float e = __expf(m_i[i] - mnew);
            m_i[i] = mnew;
            float rs = 0.f;
#pragma unroll
            for (int j = 0; j < 4; ++j) {
                float p = __expf(s[i][j] - mnew);
                s[i][j] = p; rs += p;
            }
#pragma unroll
            for (int off = 8; off > 0; off >>= 1)
                rs += __shfl_xor_sync(0xffffffffu, rs, off, 16);
            l_i[i] = l_i[i] * e + rs;
#pragma unroll
            for (int j = 0; j < 4; ++j) o[i][j] *= e;
        }

#pragma unroll
        for (int i = 0; i < 4; ++i)
#pragma unroll
            for (int j = 0; j < 4; ++j)
                Ps[(ty * 4 + i) * 65 + tx * 4 + j] = s[i][j];
        __syncthreads();

        {
            const float* gv = g_qkv + base + (size_t)(kt * 64 + lr) * QKVN
                            + 2 * DMODEL + h * DHEAD + lc;
#pragma unroll
            for (int u = 0; u < 4; ++u) {
                float4 v = *(const float4*)(gv + u * 4);
                float* d = &KVs[lr * 65 + lc + u * 4];
                d[0] = v.x; d[1] = v.y; d[2] = v.z; d[3] = v.w;
            }
        }
        __syncthreads();

#pragma unroll 4
        for (int k = 0; k < 64; ++k) {
            float pv[4], vv[4];
#pragma unroll
            for (int i = 0; i < 4; ++i) pv[i] = Ps[(ty * 4 + i) * 65 + k];
#pragma unroll
            for (int j = 0; j < 4; ++j) vv[j] = KVs[k * 65 + tx * 4 + j];
#pragma unroll
            for (int i = 0; i < 4; ++i)
#pragma unroll
                for (int j = 0; j < 4; ++j)
                    o[i][j] = fmaf(pv[i], vv[j], o[i][j]);
        }
    }

    // Epilogue: normalize, round-to-tf32 (feeds the tf32 proj GEMM)
#pragma unroll
    for (int i = 0; i < 4; ++i) {
        float inv = 1.f / l_i[i];
        float* op = out + ((size_t)b * TSEQ + qt * 64 + ty * 4 + i) * DMODEL
                        + h * DHEAD + tx * 4;
#pragma unroll
        for (int j = 0; j < 4; ++j) op[j] = round_tf32(o[i][j] * inv);
    }
}

// ---------------------------------------------------------------------------
extern "C" void kernel_launch(void* const* d_in, const int* in_sizes, int n_in,
                              void* d_out, int out_size)
{
    const float* x      = (const float*)d_in[0];   // [2,2048,1024]
    const float* w_qkv  = (const float*)d_in[1];   // [3072,1024]
    const float* w_proj = (const float*)d_in[2];   // [1024,1024]
    float* out = (float*)d_out;                    // [2,2048,1024]

    float *qkv, *attn, *xr, *wqr, *wpr;
    cudaGetSymbolAddress((void**)&qkv,  g_qkv);
    cudaGetSymbolAddress((void**)&attn, g_attn);
    cudaGetSymbolAddress((void**)&xr,   g_xr);
    cudaGetSymbolAddress((void**)&wqr,  g_wqr);
    cudaGetSymbolAddress((void**)&wpr,  g_wpr);

    cudaFuncSetAttribute(attn_kernel,
                         cudaFuncAttributeMaxDynamicSharedMemorySize, ATTN_SMEM);

    // 0) unbiased tf32 pre-rounding of GEMM operands
    {
        int n4;
        n4 = (BT * DMODEL) / 4;
        round_tf32_kernel<<<(n4 + 255) / 256, 256>>>(x, xr, n4);
        n4 = (QKVN * DMODEL) / 4;
        round_tf32_kernel<<<(n4 + 255) / 256, 256>>>(w_qkv, wqr, n4);
        n4 = (DMODEL * DMODEL) / 4;
        round_tf32_kernel<<<(n4 + 255) / 256, 256>>>(w_proj, wpr, n4);
    }

    // 1) QKV projection: [4096,3072] = xr @ wqr^T   (mma.sync tf32)
    {
        dim3 g(QKVN / 128, BT / 128);
        gemm_mma<<<g, 256>>>(xr, wqr, qkv, BT, QKVN, DMODEL);
    }

    // 2) Attention (fp32 SIMT; epilogue emits tf32-rounded values)
    {
        dim3 ga(TSEQ / 64, HEADS, NBATCH);
        attn_kernel<<<ga, 256, ATTN_SMEM>>>(attn);
    }

    // 3) Output projection: [4096,1024] = attn @ wpr^T  (mma.sync tf32)
    {
        dim3 g(DMODEL / 128, BT / 128);
        gemm_mma<<<g, 256>>>(attn, wpr, out, BT, DMODEL, DMODEL);
    }
}

// round 6
// speedup vs baseline: 3.2543x; 2.2717x over previous
#include <cuda_runtime.h>
#include <math.h>
#include <stdint.h>

#define BT     4096      // B*T
#define DMODEL 1024
#define QKVN   3072
#define HEADS  16
#define DHEAD  64
#define TSEQ   2048
#define NBATCH 2
#define NKT    (TSEQ / 64)   // 32 kv tiles

// Scratch (allocation-free rule: __device__ globals)
__device__ float g_qkv [(size_t)BT * QKVN];      // [B*T, 3D] (tf32-rounded)
__device__ float g_attn[(size_t)BT * DMODEL];    // [B*T, D] (tf32-rounded)
__device__ float g_xr  [(size_t)BT * DMODEL];    // tf32-rounded x
__device__ float g_wqr [(size_t)QKVN * DMODEL];  // tf32-rounded w_qkv
__device__ float g_wpr [(size_t)DMODEL * DMODEL];// tf32-rounded w_proj

__device__ __forceinline__ uint32_t smem_u32(const void* p) {
    uint32_t a;
    asm("{ .reg .u64 t; cvta.to.shared.u64 t, %1; cvt.u32.u64 %0, t; }"
        : "=r"(a) : "l"(p));
    return a;
}
__device__ __forceinline__ float round_tf32(float x) {
    uint32_t t;
    asm("cvt.rna.tf32.f32 %0, %1;" : "=r"(t) : "f"(x));
    return __uint_as_float(t);
}

// mma.sync m16n8k8 tf32: D += A*B  (A 16x8 row-major, B 8x8 col-major)
__device__ __forceinline__ void mma_tf32(float* d, const uint32_t* a, const uint32_t* b) {
    asm volatile(
        "mma.sync.aligned.m16n8k8.row.col.f32.tf32.tf32.f32 "
        "{%0,%1,%2,%3}, {%4,%5,%6,%7}, {%8,%9}, {%0,%1,%2,%3};"
        : "+f"(d[0]), "+f"(d[1]), "+f"(d[2]), "+f"(d[3])
        : "r"(a[0]), "r"(a[1]), "r"(a[2]), "r"(a[3]), "r"(b[0]), "r"(b[1]));
}

// ---------------------------------------------------------------------------
// C[M,N] = A[M,K] * B[N,K]^T via mma.sync tf32. (unchanged from R5, +round_out)
// ---------------------------------------------------------------------------
__global__ __launch_bounds__(256, 2) void gemm_mma(
    const float* __restrict__ A, const float* __restrict__ B,
    float* __restrict__ C, int M, int N, int K, int round_out)
{
    __shared__ float As[2][128][20];
    __shared__ float Bs[2][128][20];

    const int tid  = threadIdx.x;
    const int lane = tid & 31;
    const int wid  = tid >> 5;
    const int wm   = wid >> 2;
    const int wn   = wid & 3;
    const int bn   = blockIdx.x;
    const int bm   = blockIdx.y;
    const int KT   = K >> 4;

    const float* Ag = A + (size_t)bm * 128 * K;
    const float* Bg = B + (size_t)bn * 128 * K;

    float acc[4][4][4];
#pragma unroll
    for (int mi = 0; mi < 4; ++mi)
#pragma unroll
        for (int ni = 0; ni < 4; ++ni)
#pragma unroll
            for (int r = 0; r < 4; ++r) acc[mi][ni][r] = 0.f;

    auto fill = [&](int kt) {
        const int st = kt & 1;
        const int k0 = kt << 4;
#pragma unroll
        for (int u = 0; u < 2; ++u) {
            int f   = u * 256 + tid;
            int row = f >> 2;
            int col = (f & 3) << 2;
            uint32_t da = smem_u32(&As[st][row][col]);
            uint32_t db = smem_u32(&Bs[st][row][col]);
            const float* sa = Ag + (size_t)row * K + k0 + col;
            const float* sb = Bg + (size_t)row * K + k0 + col;
            asm volatile("cp.async.cg.shared.global [%0], [%1], 16;" :: "r"(da), "l"(sa));
            asm volatile("cp.async.cg.shared.global [%0], [%1], 16;" :: "r"(db), "l"(sb));
        }
        asm volatile("cp.async.commit_group;" ::: "memory");
    };

    fill(0);

    const int lr = lane >> 2;
    const int lc = lane & 3;

    for (int kt = 0; kt < KT; ++kt) {
        if (kt + 1 < KT) {
            fill(kt + 1);
            asm volatile("cp.async.wait_group 1;" ::: "memory");
        } else {
            asm volatile("cp.async.wait_group 0;" ::: "memory");
        }
        __syncthreads();

        const int st = kt & 1;
#pragma unroll
        for (int ks = 0; ks < 16; ks += 8) {
            uint32_t af[4][4], bf[4][2];
#pragma unroll
            for (int mi = 0; mi < 4; ++mi) {
                const int r0 = wm * 64 + mi * 16 + lr;
                af[mi][0] = __float_as_uint(As[st][r0    ][ks + lc]);
                af[mi][1] = __float_as_uint(As[st][r0 + 8][ks + lc]);
                af[mi][2] = __float_as_uint(As[st][r0    ][ks + 4 + lc]);
                af[mi][3] = __float_as_uint(As[st][r0 + 8][ks + 4 + lc]);
            }
#pragma unroll
            for (int ni = 0; ni < 4; ++ni) {
                const int n0 = wn * 32 + ni * 8 + lr;
                bf[ni][0] = __float_as_uint(Bs[st][n0][ks + lc]);
                bf[ni][1] = __float_as_uint(Bs[st][n0][ks + 4 + lc]);
            }
#pragma unroll
            for (int mi = 0; mi < 4; ++mi)
#pragma unroll
                for (int ni = 0; ni < 4; ++ni)
                    mma_tf32(acc[mi][ni], af[mi], bf[ni]);
        }
        __syncthreads();
    }

#pragma unroll
    for (int mi = 0; mi < 4; ++mi) {
#pragma unroll
        for (int ni = 0; ni < 4; ++ni) {
            const int r0 = bm * 128 + wm * 64 + mi * 16 + lr;
            const int c0 = bn * 128 + wn * 32 + ni * 8 + lc * 2;
            float v0 = acc[mi][ni][0], v1 = acc[mi][ni][1];
            float v2 = acc[mi][ni][2], v3 = acc[mi][ni][3];
            if (round_out) {
                v0 = round_tf32(v0); v1 = round_tf32(v1);
                v2 = round_tf32(v2); v3 = round_tf32(v3);
            }
            *(float2*)(C + (size_t)r0 * N + c0)       = make_float2(v0, v1);
            *(float2*)(C + (size_t)(r0 + 8) * N + c0) = make_float2(v2, v3);
        }
    }
}

// ---------------------------------------------------------------------------
// Elementwise tf32 rounding (rna).
// ---------------------------------------------------------------------------
__global__ __launch_bounds__(256) void round_tf32_kernel(
    const float* __restrict__ in, float* __restrict__ out, int n4)
{
    int i = blockIdx.x * blockDim.x + threadIdx.x;
    if (i < n4) {
        float4 v = ((const float4*)in)[i];
        v.x = round_tf32(v.x); v.y = round_tf32(v.y);
        v.z = round_tf32(v.z); v.w = round_tf32(v.w);
        ((float4*)out)[i] = v;
    }
}

// ---------------------------------------------------------------------------
// Tensor-core flash attention. Block = (b, h, 64-query tile), 256 threads.
// Warps 2(m) x 4(n): warp tile 32x16 of the 64x64 S/O tiles (2x2 m16n8k8).
// Q/K/P smem row stride 68 (conflict-free A/B-frag loads), V stride 72
// (conflict-free V-frag loads). cp.async pipeline: K prefetch +1, V double buf.
// Scale 1/8 folded into exp; softmax p values tf32-rounded for a consistent PV.
// ---------------------------------------------------------------------------
#define QS_STR  68
#define VS_STR  72
#define ATTN_SM_FLOATS (3 * 64 * QS_STR + 2 * 64 * VS_STR + 128)
#define ATTN_SMEM (ATTN_SM_FLOATS * 4)

__global__ __launch_bounds__(256, 2) void attn_mma(float* __restrict__ out)
{
    extern __shared__ float sm[];
    float* Qs  = sm;                       // [64][68]
    float* Ks  = Qs + 64 * QS_STR;         // [64][68]
    float* Ps  = Ks + 64 * QS_STR;         // [64][68]
    float* Vb  = Ps + 64 * QS_STR;         // [2][64][72]
    float* esm = Vb + 2 * 64 * VS_STR;     // [64]
    float* lsm = esm + 64;                 // [64]

    const int qt   = blockIdx.x;
    const int h    = blockIdx.y;
    const int b    = blockIdx.z;
    const int tid  = threadIdx.x;
    const int lane = tid & 31;
    const int wid  = tid >> 5;
    const int wm   = wid >> 2;      // 0..1
    const int wn   = wid & 3;       // 0..3
    const int lr   = lane >> 2;     // 0..7
    const int lc   = lane & 3;      // 0..3

    const size_t base = (size_t)b * TSEQ * QKVN;

    // async 64x64 tile load from g_qkv into smem (row stride `str` floats)
    auto load_tile = [&](float* dst, int str, int rowbase, int colbase) {
#pragma unroll
        for (int u = 0; u < 4; ++u) {
            int c   = u * 256 + tid;        // 0..1023 chunks of 16B
            int row = c >> 4;
            int col = (c & 15) << 2;
            uint32_t d = smem_u32(dst + row * str + col);
            const float* s = g_qkv + base + (size_t)(rowbase + row) * QKVN + colbase + col;
            asm volatile("cp.async.cg.shared.global [%0], [%1], 16;" :: "r"(d), "l"(s));
        }
        asm volatile("cp.async.commit_group;" ::: "memory");
    };

    // prologue: group0 = Q + K(0); group1 = V(0)
#pragma unroll
    for (int u = 0; u < 4; ++u) {  // Q part (no commit yet)
        int c   = u * 256 + tid;
        int row = c >> 4;
        int col = (c & 15) << 2;
        uint32_t d = smem_u32(Qs + row * QS_STR + col);
        const float* s = g_qkv + base + (size_t)(qt * 64 + row) * QKVN + h * DHEAD + col;
        asm volatile("cp.async.cg.shared.global [%0], [%1], 16;" :: "r"(d), "l"(s));
    }
    load_tile(Ks, QS_STR, 0, DMODEL + h * DHEAD);          // commits Q+K0
    load_tile(Vb, VS_STR, 0, 2 * DMODEL + h * DHEAD);      // commits V0

    float m_i = -INFINITY, l_i = 0.f;
    float o[2][2][4];
#pragma unroll
    for (int mi = 0; mi < 2; ++mi)
#pragma unroll
        for (int ni = 0; ni < 2; ++ni)
#pragma unroll
            for (int r = 0; r < 4; ++r) o[mi][ni][r] = 0.f;

    for (int kt = 0; kt < NKT; ++kt) {
        asm volatile("cp.async.wait_group 1;" ::: "memory");  // K(kt) (+Q) ready
        __syncthreads();  // also: all PV reads of Ps from prev iter done

        // ---- S = Q * K^T : 64x64x64 ----
        float sfr[2][2][4];
#pragma unroll
        for (int mi = 0; mi < 2; ++mi)
#pragma unroll
            for (int ni = 0; ni < 2; ++ni)
#pragma unroll
                for (int r = 0; r < 4; ++r) sfr[mi][ni][r] = 0.f;

#pragma unroll
        for (int k0 = 0; k0 < DHEAD; k0 += 8) {
            uint32_t af[2][4], bf[2][2];
#pragma unroll
            for (int mi = 0; mi < 2; ++mi) {
                const int r0 = wm * 32 + mi * 16 + lr;
                af[mi][0] = __float_as_uint(Qs[r0 * QS_STR + k0 + lc]);
                af[mi][1] = __float_as_uint(Qs[(r0 + 8) * QS_STR + k0 + lc]);
                af[mi][2] = __float_as_uint(Qs[r0 * QS_STR + k0 + 4 + lc]);
                af[mi][3] = __float_as_uint(Qs[(r0 + 8) * QS_STR + k0 + 4 + lc]);
            }
#pragma unroll
            for (int ni = 0; ni < 2; ++ni) {
                const int n0 = wn * 16 + ni * 8 + lr;
                bf[ni][0] = __float_as_uint(Ks[n0 * QS_STR + k0 + lc]);
                bf[ni][1] = __float_as_uint(Ks[n0 * QS_STR + k0 + 4 + lc]);
            }
#pragma unroll
            for (int mi = 0; mi < 2; ++mi)
#pragma unroll
                for (int ni = 0; ni < 2; ++ni)
                    mma_tf32(sfr[mi][ni], af[mi], bf[ni]);
        }

        // ---- stage S -> Ps ----
#pragma unroll
        for (int mi = 0; mi < 2; ++mi)
#pragma unroll
            for (int ni = 0; ni < 2; ++ni) {
                const int r0 = wm * 32 + mi * 16 + lr;
                const int c0 = wn * 16 + ni * 8 + lc * 2;
                *(float2*)&Ps[r0 * QS_STR + c0] =
                    make_float2(sfr[mi][ni][0], sfr[mi][ni][1]);
                *(float2*)&Ps[(r0 + 8) * QS_STR + c0] =
                    make_float2(sfr[mi][ni][2], sfr[mi][ni][3]);
            }
        __syncthreads();  // Ps visible; Ks free

        if (kt + 1 < NKT)
            load_tile(Ks, QS_STR, (kt + 1) * 64, DMODEL + h * DHEAD);

        // ---- softmax: row r = tid>>2, 4 threads/row, 16 cols each ----
        {
            const int r  = tid >> 2;
            const int c0 = (tid & 3) * 16;
            float* row = Ps + r * QS_STR + c0;
            float mx = row[0];
#pragma unroll
            for (int j = 1; j < 16; ++j) mx = fmaxf(mx, row[j]);
            mx = fmaxf(mx, __shfl_xor_sync(0xffffffffu, mx, 1));
            mx = fmaxf(mx, __shfl_xor_sync(0xffffffffu, mx, 2));
            float mnew = fmaxf(m_i, mx);
            float e = __expf(0.125f * (m_i - mnew));
            float ls = 0.f;
#pragma unroll
            for (int j = 0; j < 16; ++j) {
                float p = round_tf32(__expf(0.125f * (row[j] - mnew)));
                row[j] = p;
                ls += p;
            }
            ls += __shfl_xor_sync(0xffffffffu, ls, 1);
            ls += __shfl_xor_sync(0xffffffffu, ls, 2);
            l_i = l_i * e + ls;
            m_i = mnew;
            if ((tid & 3) == 0) esm[r] = e;
        }

        if (kt + 1 < NKT)
            asm volatile("cp.async.wait_group 1;" ::: "memory");  // V(kt) ready
        else
            asm volatile("cp.async.wait_group 0;" ::: "memory");
        __syncthreads();  // V(kt) + softmax results visible

        if (kt + 1 < NKT)
            load_tile(Vb + ((kt + 1) & 1) * 64 * VS_STR, VS_STR,
                      (kt + 1) * 64, 2 * DMODEL + h * DHEAD);

        // ---- rescale O by e[row] ----
#pragma unroll
        for (int mi = 0; mi < 2; ++mi) {
            const int r0 = wm * 32 + mi * 16 + lr;
            const float e0 = esm[r0];
            const float e1 = esm[r0 + 8];
#pragma unroll
            for (int ni = 0; ni < 2; ++ni) {
                o[mi][ni][0] *= e0; o[mi][ni][1] *= e0;
                o[mi][ni][2] *= e1; o[mi][ni][3] *= e1;
            }
        }

        // ---- O += P * V : 64x64x64 ----
        const float* Vs = Vb + (kt & 1) * 64 * VS_STR;
#pragma unroll
        for (int k0 = 0; k0 < 64; k0 += 8) {
            uint32_t af[2][4], bf[2][2];
#pragma unroll
            for (int mi = 0; mi < 2; ++mi) {
                const int r0 = wm * 32 + mi * 16 + lr;
                af[mi][0] = __float_as_uint(Ps[r0 * QS_STR + k0 + lc]);
                af[mi][1] = __float_as_uint(Ps[(r0 + 8) * QS_STR + k0 + lc]);
                af[mi][2] = __float_as_uint(Ps[r0 * QS_STR + k0 + 4 + lc]);
                af[mi][3] = __float_as_uint(Ps[(r0 + 8) * QS_STR + k0 + 4 + lc]);
            }
#pragma unroll
            for (int ni = 0; ni < 2; ++ni) {
                const int n0 = wn * 16 + ni * 8 + lr;
                bf[ni][0] = __float_as_uint(Vs[(k0 + lc) * VS_STR + n0]);
                bf[ni][1] = __float_as_uint(Vs[(k0 + 4 + lc) * VS_STR + n0]);
            }
#pragma unroll
            for (int mi = 0; mi < 2; ++mi)
#pragma unroll
                for (int ni = 0; ni < 2; ++ni)
                    mma_tf32(o[mi][ni], af[mi], bf[ni]);
        }
    }

    // ---- epilogue: normalize by 1/l, tf32-round, write ----
    if ((tid & 3) == 0) lsm[tid >> 2] = l_i;
    __syncthreads();

#pragma unroll
    for (int mi = 0; mi < 2; ++mi) {
        const int r0 = wm * 32 + mi * 16 + lr;
        const float inv0 = 1.f / lsm[r0];
        const float inv1 = 1.f / lsm[r0 + 8];
#pragma unroll
        for (int ni = 0; ni < 2; ++ni) {
            const int c0 = wn * 16 + ni * 8 + lc * 2;
            float* p0 = out + ((size_t)b * TSEQ + qt * 64 + r0) * DMODEL + h * DHEAD + c0;
            float* p1 = out + ((size_t)b * TSEQ + qt * 64 + r0 + 8) * DMODEL + h * DHEAD + c0;
            *(float2*)p0 = make_float2(round_tf32(o[mi][ni][0] * inv0),
                                       round_tf32(o[mi][ni][1] * inv0));
            *(float2*)p1 = make_float2(round_tf32(o[mi][ni][2] * inv1),
                                       round_tf32(o[mi][ni][3] * inv1));
        }
    }
}

// ---------------------------------------------------------------------------
extern "C" void kernel_launch(void* const* d_in, const int* in_sizes, int n_in,
                              void* d_out, int out_size)
{
    const float* x      = (const float*)d_in[0];   // [2,2048,1024]
    const float* w_qkv  = (const float*)d_in[1];   // [3072,1024]
    const float* w_proj = (const float*)d_in[2];   // [1024,1024]
    float* out = (float*)d_out;                    // [2,2048,1024]

    float *qkv, *attn, *xr, *wqr, *wpr;
    cudaGetSymbolAddress((void**)&qkv,  g_qkv);
    cudaGetSymbolAddress((void**)&attn, g_attn);
    cudaGetSymbolAddress((void**)&xr,   g_xr);
    cudaGetSymbolAddress((void**)&wqr,  g_wqr);
    cudaGetSymbolAddress((void**)&wpr,  g_wpr);

    cudaFuncSetAttribute(attn_mma,
                         cudaFuncAttributeMaxDynamicSharedMemorySize, ATTN_SMEM);

    // 0) unbiased tf32 pre-rounding of GEMM operands
    {
        int n4;
        n4 = (BT * DMODEL) / 4;
        round_tf32_kernel<<<(n4 + 255) / 256, 256>>>(x, xr, n4);
        n4 = (QKVN * DMODEL) / 4;
        round_tf32_kernel<<<(n4 + 255) / 256, 256>>>(w_qkv, wqr, n4);
        n4 = (DMODEL * DMODEL) / 4;
        round_tf32_kernel<<<(n4 + 255) / 256, 256>>>(w_proj, wpr, n4);
    }

    // 1) QKV projection (tf32-rounded output -> exact attention operands)
    {
        dim3 g(QKVN / 128, BT / 128);
        gemm_mma<<<g, 256>>>(xr, wqr, qkv, BT, QKVN, DMODEL, 1);
    }

    // 2) Tensor-core flash attention
    {
        dim3 ga(TSEQ / 64, HEADS, NBATCH);
        attn_mma<<<ga, 256, ATTN_SMEM>>>(attn);
    }

    // 3) Output projection (full fp32 output)
    {
        dim3 g(DMODEL / 128, BT / 128);
        gemm_mma<<<g, 256>>>(attn, wpr, out, BT, DMODEL, DMODEL, 0);
    }
}

// round 8
// speedup vs baseline: 3.2632x; 1.0027x over previous
#include <cuda_runtime.h>
#include <math.h>
#include <stdint.h>

#define BT     4096      // B*T
#define DMODEL 1024
#define QKVN   3072
#define HEADS  16
#define DHEAD  64
#define TSEQ   2048
#define NBATCH 2
#define NKT    (TSEQ / 64)   // 32 kv tiles

// Scratch (allocation-free rule: __device__ globals)
__device__ float g_qkv [(size_t)BT * QKVN];      // [B*T, 3D] (tf32-rounded)
__device__ float g_attn[(size_t)BT * DMODEL];    // [B*T, D] (tf32-rounded)
__device__ float g_xr  [(size_t)BT * DMODEL];    // tf32-rounded x
__device__ float g_wqr [(size_t)QKVN * DMODEL];  // tf32-rounded w_qkv
__device__ float g_wpr [(size_t)DMODEL * DMODEL];// tf32-rounded w_proj

__device__ __forceinline__ uint32_t smem_u32(const void* p) {
    uint32_t a;
    asm("{ .reg .u64 t; cvta.to.shared.u64 t, %1; cvt.u32.u64 %0, t; }"
        : "=r"(a) : "l"(p));
    return a;
}
__device__ __forceinline__ float round_tf32(float x) {
    uint32_t t;
    asm("cvt.rna.tf32.f32 %0, %1;" : "=r"(t) : "f"(x));
    return __uint_as_float(t);
}

// mma.sync m16n8k8 tf32: D += A*B  (A 16x8 row-major, B 8x8 col-major)
__device__ __forceinline__ void mma_tf32(float* d, const uint32_t* a, const uint32_t* b) {
    asm volatile(
        "mma.sync.aligned.m16n8k8.row.col.f32.tf32.tf32.f32 "
        "{%0,%1,%2,%3}, {%4,%5,%6,%7}, {%8,%9}, {%0,%1,%2,%3};"
        : "+f"(d[0]), "+f"(d[1]), "+f"(d[2]), "+f"(d[3])
        : "r"(a[0]), "r"(a[1]), "r"(a[2]), "r"(a[3]), "r"(b[0]), "r"(b[1]));
}

// ---------------------------------------------------------------------------
// C[M,N] = A[M,K] * B[N,K]^T via mma.sync tf32.
// 128x128 CTA tile, BK=16, 4-stage cp.async pipeline (3-deep prefetch),
// ONE __syncthreads per k-chunk. 8 warps 2(m)x4(n), warp tile 64x32.
// Dynamic smem: 4 stages * (A[128][20]+B[128][20]) * 4B = 81920 B.
// ---------------------------------------------------------------------------
#define GSTG_FLOATS (2 * 128 * 20)            // floats per stage (A+B)
#define GEMM_SMEM   (4 * GSTG_FLOATS * 4)     // 81920 bytes

__global__ __launch_bounds__(256, 2) void gemm_mma(
    const float* __restrict__ A, const float* __restrict__ B,
    float* __restrict__ C, int M, int N, int K, int round_out)
{
    extern __shared__ float gsm[];

    const int tid  = threadIdx.x;
    const int lane = tid & 31;
    const int wid  = tid >> 5;
    const int wm   = wid >> 2;
    const int wn   = wid & 3;
    const int bn   = blockIdx.x;
    const int bm   = blockIdx.y;
    const int KT   = K >> 4;

    const float* Ag = A + (size_t)bm * 128 * K;
    const float* Bg = B + (size_t)bn * 128 * K;

    float acc[4][4][4];
#pragma unroll
    for (int mi = 0; mi < 4; ++mi)
#pragma unroll
        for (int ni = 0; ni < 4; ++ni)
#pragma unroll
            for (int r = 0; r < 4; ++r) acc[mi][ni][r] = 0.f;

    auto fill = [&](int kt) {
        const int st = kt & 3;
        float* sA = gsm + st * GSTG_FLOATS;
        float* sB = sA + 128 * 20;
        const int k0 = kt << 4;
#pragma unroll
        for (int u = 0; u < 2; ++u) {
            int f   = u * 256 + tid;       // 0..511
            int row = f >> 2;
            int col = (f & 3) << 2;
            uint32_t da = smem_u32(sA + row * 20 + col);
            uint32_t db = smem_u32(sB + row * 20 + col);
            const float* sa = Ag + (size_t)row * K + k0 + col;
            const float* sb = Bg + (size_t)row * K + k0 + col;
            asm volatile("cp.async.cg.shared.global [%0], [%1], 16;" :: "r"(da), "l"(sa));
            asm volatile("cp.async.cg.shared.global [%0], [%1], 16;" :: "r"(db), "l"(sb));
        }
        asm volatile("cp.async.commit_group;" ::: "memory");
    };

    // 3-deep prologue
    fill(0); fill(1); fill(2);

    const int lr = lane >> 2;
    const int lc = lane & 3;

    for (int kt = 0; kt < KT; ++kt) {
        // wait for chunk kt (tail-aware pending count)
        const int rem = KT - 1 - kt;
        if (rem >= 2)      asm volatile("cp.async.wait_group 2;" ::: "memory");
        else if (rem == 1) asm volatile("cp.async.wait_group 1;" ::: "memory");
        else               asm volatile("cp.async.wait_group 0;" ::: "memory");
        __syncthreads();  // chunk kt visible; also: all warps done reading stage (kt-1)%4

        // prefetch chunk kt+3 into stage (kt-1)%4 (safe after the sync above)
        if (kt + 3 < KT) fill(kt + 3);

        const int st = kt & 3;
        const float* sA = gsm + st * GSTG_FLOATS;
        const float* sB = sA + 128 * 20;
#pragma unroll
        for (int ks = 0; ks < 16; ks += 8) {
            uint32_t af[4][4], bf[4][2];
#pragma unroll
            for (int mi = 0; mi < 4; ++mi) {
                const int r0 = wm * 64 + mi * 16 + lr;
                af[mi][0] = __float_as_uint(sA[r0 * 20 + ks + lc]);
                af[mi][1] = __float_as_uint(sA[(r0 + 8) * 20 + ks + lc]);
                af[mi][2] = __float_as_uint(sA[r0 * 20 + ks + 4 + lc]);
                af[mi][3] = __float_as_uint(sA[(r0 + 8) * 20 + ks + 4 + lc]);
            }
#pragma unroll
            for (int ni = 0; ni < 4; ++ni) {
                const int n0 = wn * 32 + ni * 8 + lr;
                bf[ni][0] = __float_as_uint(sB[n0 * 20 + ks + lc]);
                bf[ni][1] = __float_as_uint(sB[n0 * 20 + ks + 4 + lc]);
            }
#pragma unroll
            for (int mi = 0; mi < 4; ++mi)
#pragma unroll
                for (int ni = 0; ni < 4; ++ni)
                    mma_tf32(acc[mi][ni], af[mi], bf[ni]);
        }
    }

#pragma unroll
    for (int mi = 0; mi < 4; ++mi) {
#pragma unroll
        for (int ni = 0; ni < 4; ++ni) {
            const int r0 = bm * 128 + wm * 64 + mi * 16 + lr;
            const int c0 = bn * 128 + wn * 32 + ni * 8 + lc * 2;
            float v0 = acc[mi][ni][0], v1 = acc[mi][ni][1];
            float v2 = acc[mi][ni][2], v3 = acc[mi][ni][3];
            if (round_out) {
                v0 = round_tf32(v0); v1 = round_tf32(v1);
                v2 = round_tf32(v2); v3 = round_tf32(v3);
            }
            *(float2*)(C + (size_t)r0 * N + c0)       = make_float2(v0, v1);
            *(float2*)(C + (size_t)(r0 + 8) * N + c0) = make_float2(v2, v3);
        }
    }
}

// ---------------------------------------------------------------------------
// Merged unbiased tf32 pre-rounding of all three GEMM operand tensors.
// ---------------------------------------------------------------------------
#define X4  ((BT * DMODEL) / 4)
#define WQ4 ((QKVN * DMODEL) / 4)
#define WP4 ((DMODEL * DMODEL) / 4)

__global__ __launch_bounds__(256) void round_all_kernel(
    const float* __restrict__ x, const float* __restrict__ wq,
    const float* __restrict__ wp, float* __restrict__ xr,
    float* __restrict__ wqr, float* __restrict__ wpr)
{
    int i = blockIdx.x * blockDim.x + threadIdx.x;
    const float4* src;
    float4* dst;
    int j;
    if (i < X4)             { src = (const float4*)x;  dst = (float4*)xr;  j = i; }
    else if (i < X4 + WQ4)  { src = (const float4*)wq; dst = (float4*)wqr; j = i - X4; }
    else if (i < X4 + WQ4 + WP4) { src = (const float4*)wp; dst = (float4*)wpr; j = i - X4 - WQ4; }
    else return;
    float4 v = src[j];
    v.x = round_tf32(v.x); v.y = round_tf32(v.y);
    v.z = round_tf32(v.z); v.w = round_tf32(v.w);
    dst[j] = v;
}

// ---------------------------------------------------------------------------
// Tensor-core flash attention (unchanged from R6 — passing at ~355us).
// ---------------------------------------------------------------------------
#define QS_STR  68
#define VS_STR  72
#define ATTN_SM_FLOATS (3 * 64 * QS_STR + 2 * 64 * VS_STR + 128)
#define ATTN_SMEM (ATTN_SM_FLOATS * 4)

__global__ __launch_bounds__(256, 2) void attn_mma(float* __restrict__ out)
{
    extern __shared__ float sm[];
    float* Qs  = sm;                       // [64][68]
    float* Ks  = Qs + 64 * QS_STR;         // [64][68]
    float* Ps  = Ks + 64 * QS_STR;         // [64][68]
    float* Vb  = Ps + 64 * QS_STR;         // [2][64][72]
    float* esm = Vb + 2 * 64 * VS_STR;     // [64]
    float* lsm = esm + 64;                 // [64]

    const int qt   = blockIdx.x;
    const int h    = blockIdx.y;
    const int b    = blockIdx.z;
    const int tid  = threadIdx.x;
    const int lane = tid & 31;
    const int wid  = tid >> 5;
    const int wm   = wid >> 2;      // 0..1
    const int wn   = wid & 3;       // 0..3
    const int lr   = lane >> 2;     // 0..7
    const int lc   = lane & 3;      // 0..3

    const size_t base = (size_t)b * TSEQ * QKVN;

    auto load_tile = [&](float* dst, int str, int rowbase, int colbase) {
#pragma unroll
        for (int u = 0; u < 4; ++u) {
            int c   = u * 256 + tid;
            int row = c >> 4;
            int col = (c & 15) << 2;
            uint32_t d = smem_u32(dst + row * str + col);
            const float* s = g_qkv + base + (size_t)(rowbase + row) * QKVN + colbase + col;
            asm volatile("cp.async.cg.shared.global [%0], [%1], 16;" :: "r"(d), "l"(s));
        }
        asm volatile("cp.async.commit_group;" ::: "memory");
    };

    // prologue: group0 = Q + K(0); group1 = V(0)
#pragma unroll
    for (int u = 0; u < 4; ++u) {
        int c   = u * 256 + tid;
        int row = c >> 4;
        int col = (c & 15) << 2;
        uint32_t d = smem_u32(Qs + row * QS_STR + col);
        const float* s = g_qkv + base + (size_t)(qt * 64 + row) * QKVN + h * DHEAD + col;
        asm volatile("cp.async.cg.shared.global [%0], [%1], 16;" :: "r"(d), "l"(s));
    }
    load_tile(Ks, QS_STR, 0, DMODEL + h * DHEAD);
    load_tile(Vb, VS_STR, 0, 2 * DMODEL + h * DHEAD);

    float m_i = -INFINITY, l_i = 0.f;
    float o[2][2][4];
#pragma unroll
    for (int mi = 0; mi < 2; ++mi)
#pragma unroll
        for (int ni = 0; ni < 2; ++ni)
#pragma unroll
            for (int r = 0; r < 4; ++r) o[mi][ni][r] = 0.f;

    for (int kt = 0; kt < NKT; ++kt) {
        asm volatile("cp.async.wait_group 1;" ::: "memory");
        __syncthreads();

        // ---- S = Q * K^T ----
        float sfr[2][2][4];
#pragma unroll
        for (int mi = 0; mi < 2; ++mi)
#pragma unroll
            for (int ni = 0; ni < 2; ++ni)
#pragma unroll
                for (int r = 0; r < 4; ++r) sfr[mi][ni][r] = 0.f;

#pragma unroll
        for (int k0 = 0; k0 < DHEAD; k0 += 8) {
            uint32_t af[2][4], bf[2][2];
#pragma unroll
            for (int mi = 0; mi < 2; ++mi) {
                const int r0 = wm * 32 + mi * 16 + lr;
                af[mi][0] = __float_as_uint(Qs[r0 * QS_STR + k0 + lc]);
                af[mi][1] = __float_as_uint(Qs[(r0 + 8) * QS_STR + k0 + lc]);
                af[mi][2] = __float_as_uint(Qs[r0 * QS_STR + k0 + 4 + lc]);
                af[mi][3] = __float_as_uint(Qs[(r0 + 8) * QS_STR + k0 + 4 + lc]);
            }
#pragma unroll
            for (int ni = 0; ni < 2; ++ni) {
                const int n0 = wn * 16 + ni * 8 + lr;
                bf[ni][0] = __float_as_uint(Ks[n0 * QS_STR + k0 + lc]);
                bf[ni][1] = __float_as_uint(Ks[n0 * QS_STR + k0 + 4 + lc]);
            }
#pragma unroll
            for (int mi = 0; mi < 2; ++mi)
#pragma unroll
                for (int ni = 0; ni < 2; ++ni)
                    mma_tf32(sfr[mi][ni], af[mi], bf[ni]);
        }

        // ---- stage S -> Ps ----
#pragma unroll
        for (int mi = 0; mi < 2; ++mi)
#pragma unroll
            for (int ni = 0; ni < 2; ++ni) {
                const int r0 = wm * 32 + mi * 16 + lr;
                const int c0 = wn * 16 + ni * 8 + lc * 2;
                *(float2*)&Ps[r0 * QS_STR + c0] =
                    make_float2(sfr[mi][ni][0], sfr[mi][ni][1]);
                *(float2*)&Ps[(r0 + 8) * QS_STR + c0] =
                    make_float2(sfr[mi][ni][2], sfr[mi][ni][3]);
            }
        __syncthreads();

        if (kt + 1 < NKT)
            load_tile(Ks, QS_STR, (kt + 1) * 64, DMODEL + h * DHEAD);

        // ---- softmax ----
        {
            const int r  = tid >> 2;
            const int c0 = (tid & 3) * 16;
            float* row = Ps + r * QS_STR + c0;
            float mx = row[0];
#pragma unroll
            for (int j = 1; j < 16; ++j) mx = fmaxf(mx, row[j]);
            mx = fmaxf(mx, __shfl_xor_sync(0xffffffffu, mx, 1));
            mx = fmaxf(mx, __shfl_xor_sync(0xffffffffu, mx, 2));
            float mnew = fmaxf(m_i, mx);
            float e = __expf(0.125f * (m_i - mnew));
            float ls = 0.f;
#pragma unroll
            for (int j = 0; j < 16; ++j) {
                float p = round_tf32(__expf(0.125f * (row[j] - mnew)));
                row[j] = p;
                ls += p;
            }
            ls += __shfl_xor_sync(0xffffffffu, ls, 1);
            ls += __shfl_xor_sync(0xffffffffu, ls, 2);
            l_i = l_i * e + ls;
            m_i = mnew;
            if ((tid & 3) == 0) esm[r] = e;
        }

        if (kt + 1 < NKT)
            asm volatile("cp.async.wait_group 1;" ::: "memory");
        else
            asm volatile("cp.async.wait_group 0;" ::: "memory");
        __syncthreads();

        if (kt + 1 < NKT)
            load_tile(Vb + ((kt + 1) & 1) * 64 * VS_STR, VS_STR,
                      (kt + 1) * 64, 2 * DMODEL + h * DHEAD);

        // ---- rescale O ----
#pragma unroll
        for (int mi = 0; mi < 2; ++mi) {
            const int r0 = wm * 32 + mi * 16 + lr;
            const float e0 = esm[r0];
            const float e1 = esm[r0 + 8];
#pragma unroll
            for (int ni = 0; ni < 2; ++ni) {
                o[mi][ni][0] *= e0; o[mi][ni][1] *= e0;
                o[mi][ni][2] *= e1; o[mi][ni][3] *= e1;
            }
        }

        // ---- O += P * V ----
        const float* Vs = Vb + (kt & 1) * 64 * VS_STR;
#pragma unroll
        for (int k0 = 0; k0 < 64; k0 += 8) {
            uint32_t af[2][4], bf[2][2];
#pragma unroll
            for (int mi = 0; mi < 2; ++mi) {
                const int r0 = wm * 32 + mi * 16 + lr;
                af[mi][0] = __float_as_uint(Ps[r0 * QS_STR + k0 + lc]);
                af[mi][1] = __float_as_uint(Ps[(r0 + 8) * QS_STR + k0 + lc]);
                af[mi][2] = __float_as_uint(Ps[r0 * QS_STR + k0 + 4 + lc]);
                af[mi][3] = __float_as_uint(Ps[(r0 + 8) * QS_STR + k0 + 4 + lc]);
            }
#pragma unroll
            for (int ni = 0; ni < 2; ++ni) {
                const int n0 = wn * 16 + ni * 8 + lr;
                bf[ni][0] = __float_as_uint(Vs[(k0 + lc) * VS_STR + n0]);
                bf[ni][1] = __float_as_uint(Vs[(k0 + 4 + lc) * VS_STR + n0]);
            }
#pragma unroll
            for (int mi = 0; mi < 2; ++mi)
#pragma unroll
                for (int ni = 0; ni < 2; ++ni)
                    mma_tf32(o[mi][ni], af[mi], bf[ni]);
        }
    }

    // ---- epilogue ----
    if ((tid & 3) == 0) lsm[tid >> 2] = l_i;
    __syncthreads();

#pragma unroll
    for (int mi = 0; mi < 2; ++mi) {
        const int r0 = wm * 32 + mi * 16 + lr;
        const float inv0 = 1.f / lsm[r0];
        const float inv1 = 1.f / lsm[r0 + 8];
#pragma unroll
        for (int ni = 0; ni < 2; ++ni) {
            const int c0 = wn * 16 + ni * 8 + lc * 2;
            float* p0 = out + ((size_t)b * TSEQ + qt * 64 + r0) * DMODEL + h * DHEAD + c0;
            float* p1 = out + ((size_t)b * TSEQ + qt * 64 + r0 + 8) * DMODEL + h * DHEAD + c0;
            *(float2*)p0 = make_float2(round_tf32(o[mi][ni][0] * inv0),
                                       round_tf32(o[mi][ni][1] * inv0));
            *(float2*)p1 = make_float2(round_tf32(o[mi][ni][2] * inv1),
                                       round_tf32(o[mi][ni][3] * inv1));
        }
    }
}

// ---------------------------------------------------------------------------
extern "C" void kernel_launch(void* const* d_in, const int* in_sizes, int n_in,
                              void* d_out, int out_size)
{
    const float* x      = (const float*)d_in[0];   // [2,2048,1024]
    const float* w_qkv  = (const float*)d_in[1];   // [3072,1024]
    const float* w_proj = (const float*)d_in[2];   // [1024,1024]
    float* out = (float*)d_out;                    // [2,2048,1024]

    float *qkv, *attn, *xr, *wqr, *wpr;
    cudaGetSymbolAddress((void**)&qkv,  g_qkv);
    cudaGetSymbolAddress((void**)&attn, g_attn);
    cudaGetSymbolAddress((void**)&xr,   g_xr);
    cudaGetSymbolAddress((void**)&wqr,  g_wqr);
    cudaGetSymbolAddress((void**)&wpr,  g_wpr);

    cudaFuncSetAttribute(gemm_mma,
                         cudaFuncAttributeMaxDynamicSharedMemorySize, GEMM_SMEM);
    cudaFuncSetAttribute(attn_mma,
                         cudaFuncAttributeMaxDynamicSharedMemorySize, ATTN_SMEM);

    // 0) unbiased tf32 pre-rounding of all GEMM operands (one launch)
    {
        int total = X4 + WQ4 + WP4;
        round_all_kernel<<<(total + 255) / 256, 256>>>(x, w_qkv, w_proj, xr, wqr, wpr);
    }

    // 1) QKV projection (tf32-rounded output -> exact attention operands)
    {
        dim3 g(QKVN / 128, BT / 128);
        gemm_mma<<<g, 256, GEMM_SMEM>>>(xr, wqr, qkv, BT, QKVN, DMODEL, 1);
    }

    // 2) Tensor-core flash attention
    {
        dim3 ga(TSEQ / 64, HEADS, NBATCH);
        attn_mma<<<ga, 256, ATTN_SMEM>>>(attn);
    }

    // 3) Output projection (full fp32 output)
    {
        dim3 g(DMODEL / 128, BT / 128);
        gemm_mma<<<g, 256, GEMM_SMEM>>>(attn, wpr, out, BT, DMODEL, DMODEL, 0);
    }
}

// round 10
// speedup vs baseline: 4.4485x; 1.3632x over previous
#include <cuda_runtime.h>
#include <cuda_fp16.h>
#include <math.h>
#include <stdint.h>

#define BT     4096      // B*T
#define DMODEL 1024
#define QKVN   3072
#define HEADS  16
#define DHEAD  64
#define TSEQ   2048
#define NBATCH 2
#define NKT    (TSEQ / 64)   // 32 kv tiles

// Scratch (allocation-free rule: __device__ globals)
__device__ __half g_qkvh [(size_t)BT * QKVN];      // fp16 qkv
__device__ __half g_attnh[(size_t)BT * DMODEL];    // fp16 attention out
__device__ __half g_xh   [(size_t)BT * DMODEL];    // fp16 x
__device__ __half g_wqh  [(size_t)QKVN * DMODEL];  // fp16 w_qkv
__device__ __half g_wph  [(size_t)DMODEL * DMODEL];// fp16 w_proj

__device__ __forceinline__ uint32_t smem_u32(const void* p) {
    uint32_t a;
    asm("{ .reg .u64 t; cvta.to.shared.u64 t, %1; cvt.u32.u64 %0, t; }"
        : "=r"(a) : "l"(p));
    return a;
}

// mma.sync m16n8k16 fp16 with fp32 accumulate
__device__ __forceinline__ void mma_f16(float* d, const uint32_t* a, const uint32_t* b) {
    asm volatile(
        "mma.sync.aligned.m16n8k16.row.col.f32.f16.f16.f32 "
        "{%0,%1,%2,%3}, {%4,%5,%6,%7}, {%8,%9}, {%0,%1,%2,%3};"
        : "+f"(d[0]), "+f"(d[1]), "+f"(d[2]), "+f"(d[3])
        : "r"(a[0]), "r"(a[1]), "r"(a[2]), "r"(a[3]), "r"(b[0]), "r"(b[1]));
}

__device__ __forceinline__ void ldsm_x4(uint32_t* r, uint32_t addr) {
    asm volatile("ldmatrix.sync.aligned.m8n8.x4.shared.b16 {%0,%1,%2,%3}, [%4];"
        : "=r"(r[0]), "=r"(r[1]), "=r"(r[2]), "=r"(r[3]) : "r"(addr));
}
__device__ __forceinline__ void ldsm_x2(uint32_t* r, uint32_t addr) {
    asm volatile("ldmatrix.sync.aligned.m8n8.x2.shared.b16 {%0,%1}, [%2];"
        : "=r"(r[0]), "=r"(r[1]) : "r"(addr));
}
__device__ __forceinline__ void ldsm_x2_t(uint32_t* r, uint32_t addr) {
    asm volatile("ldmatrix.sync.aligned.m8n8.x2.trans.shared.b16 {%0,%1}, [%2];"
        : "=r"(r[0]), "=r"(r[1]) : "r"(addr));
}

// ---------------------------------------------------------------------------
// C[M,N] = A[M,K] * B[N,K]^T, fp16 operands, fp32 accum.
// 128x128 CTA tile, BK=32 halves (2 x k16 mma steps), 4-stage cp.async,
// one __syncthreads per chunk. 8 warps 2(m)x4(n), warp tile 64x32.
// smem row stride 40 halves (20 words -> conflict-free ldmatrix).
// Dyn smem: 4 stages * 2 * 128 * 40 halves * 2B = 81920 B.
// ---------------------------------------------------------------------------
#define GS   40
#define GSTG (2 * 128 * GS)          // halves per stage (A+B)
#define GEMM_SMEM (4 * GSTG * 2)     // bytes

__global__ __launch_bounds__(256, 2) void gemm_f16(
    const __half* __restrict__ A, const __half* __restrict__ B,
    float* __restrict__ Cf, __half* __restrict__ Ch, int M, int N, int K)
{
    extern __shared__ __half gsm[];

    const int tid  = threadIdx.x;
    const int lane = tid & 31;
    const int wid  = tid >> 5;
    const int wm   = wid >> 2;
    const int wn   = wid & 3;
    const int bn   = blockIdx.x;
    const int bm   = blockIdx.y;
    const int KT   = K >> 5;            // BK = 32 halves

    const __half* Ag = A + (size_t)bm * 128 * K;
    const __half* Bg = B + (size_t)bn * 128 * K;

    float acc[4][4][4];
#pragma unroll
    for (int mi = 0; mi < 4; ++mi)
#pragma unroll
        for (int ni = 0; ni < 4; ++ni)
#pragma unroll
            for (int r = 0; r < 4; ++r) acc[mi][ni][r] = 0.f;

    auto fill = [&](int kt) {
        const int st = kt & 3;
        __half* sA = gsm + st * GSTG;
        __half* sB = sA + 128 * GS;
        const int k0 = kt << 5;
#pragma unroll
        for (int u = 0; u < 2; ++u) {
            int f   = u * 256 + tid;        // 0..511
            int row = f >> 2;
            int col = (f & 3) << 3;         // 8 halves = 16B
            uint32_t da = smem_u32(sA + row * GS + col);
            uint32_t db = smem_u32(sB + row * GS + col);
            const __half* sa = Ag + (size_t)row * K + k0 + col;
            const __half* sb = Bg + (size_t)row * K + k0 + col;
            asm volatile("cp.async.cg.shared.global [%0], [%1], 16;" :: "r"(da), "l"(sa));
            asm volatile("cp.async.cg.shared.global [%0], [%1], 16;" :: "r"(db), "l"(sb));
        }
        asm volatile("cp.async.commit_group;" ::: "memory");
    };

    fill(0); fill(1); fill(2);

    const int lane15 = lane & 15;
    const int a_col  = (lane >> 4) << 3;       // 0 / 8 (k-hi select for x4)
    const int b_row  = lane & 7;
    const int b_col  = ((lane >> 3) & 1) << 3; // 0 / 8 (k-hi select for x2)
    const int lr = lane >> 2;
    const int lc = lane & 3;

    for (int kt = 0; kt < KT; ++kt) {
        const int rem = KT - 1 - kt;
        if (rem >= 2)      asm volatile("cp.async.wait_group 2;" ::: "memory");
        else if (rem == 1) asm volatile("cp.async.wait_group 1;" ::: "memory");
        else               asm volatile("cp.async.wait_group 0;" ::: "memory");
        __syncthreads();

        if (kt + 3 < KT) fill(kt + 3);

        const int st = kt & 3;
        const __half* sA = gsm + st * GSTG;
        const __half* sB = sA + 128 * GS;
#pragma unroll
        for (int ks = 0; ks < 2; ++ks) {
            const int k0 = ks << 4;
            uint32_t af[4][4], bf[4][2];
#pragma unroll
            for (int mi = 0; mi < 4; ++mi)
                ldsm_x4(af[mi], smem_u32(sA + (wm * 64 + mi * 16 + lane15) * GS
                                            + k0 + a_col));
#pragma unroll
            for (int ni = 0; ni < 4; ++ni)
                ldsm_x2(bf[ni], smem_u32(sB + (wn * 32 + ni * 8 + b_row) * GS
                                            + k0 + b_col));
#pragma unroll
            for (int mi = 0; mi < 4; ++mi)
#pragma unroll
                for (int ni = 0; ni < 4; ++ni)
                    mma_f16(acc[mi][ni], af[mi], bf[ni]);
        }
    }

#pragma unroll
    for (int mi = 0; mi < 4; ++mi) {
#pragma unroll
        for (int ni = 0; ni < 4; ++ni) {
            const int r0 = bm * 128 + wm * 64 + mi * 16 + lr;
            const int c0 = bn * 128 + wn * 32 + ni * 8 + lc * 2;
            if (Ch) {
                *(__half2*)(Ch + (size_t)r0 * N + c0) =
                    __floats2half2_rn(acc[mi][ni][0], acc[mi][ni][1]);
                *(__half2*)(Ch + (size_t)(r0 + 8) * N + c0) =
                    __floats2half2_rn(acc[mi][ni][2], acc[mi][ni][3]);
            } else {
                *(float2*)(Cf + (size_t)r0 * N + c0) =
                    make_float2(acc[mi][ni][0], acc[mi][ni][1]);
                *(float2*)(Cf + (size_t)(r0 + 8) * N + c0) =
                    make_float2(acc[mi][ni][2], acc[mi][ni][3]);
            }
        }
    }
}

// ---------------------------------------------------------------------------
// Merged f32 -> fp16 conversion of all three operand tensors.
// ---------------------------------------------------------------------------
#define X4  ((BT * DMODEL) / 4)
#define WQ4 ((QKVN * DMODEL) / 4)
#define WP4 ((DMODEL * DMODEL) / 4)

__global__ __launch_bounds__(256) void cvt_all_kernel(
    const float* __restrict__ x, const float* __restrict__ wq,
    const float* __restrict__ wp)
{
    int i = blockIdx.x * blockDim.x + threadIdx.x;
    const float4* src;
    __half2* dst;
    int j;
    if (i < X4)                  { src = (const float4*)x;  dst = (__half2*)g_xh;  j = i; }
    else if (i < X4 + WQ4)       { src = (const float4*)wq; dst = (__half2*)g_wqh; j = i - X4; }
    else if (i < X4 + WQ4 + WP4) { src = (const float4*)wp; dst = (__half2*)g_wph; j = i - X4 - WQ4; }
    else return;
    float4 v = src[j];
    dst[2 * j]     = __floats2half2_rn(v.x, v.y);
    dst[2 * j + 1] = __floats2half2_rn(v.z, v.w);
}

// ---------------------------------------------------------------------------
// fp16 tensor-core flash attention. Block = (b, h, 64-query tile), 256 thr.
// Warps 2(m) x 4(n), warp tile 32x16 (2x2 m16n8k16 over k-chunks of 16).
// Tiles Q/K/V/P as fp16 (stride 72 halves); S staged as f32 (stride 68).
// V fragments via ldmatrix.x2.trans. S accum + softmax + O accum all fp32.
// ---------------------------------------------------------------------------
#define AQS 72   // half stride
#define SFS 68   // float stride
// bytes: 5 half tiles (Q,K,V0,V1,P) * 64*72*2 + Sf 64*68*4 + esm/lsm 512
#define ATTN_SMEM (5 * 64 * AQS * 2 + 64 * SFS * 4 + 512)

__global__ __launch_bounds__(256, 2) void attn_f16(__half* __restrict__ out)
{
    extern __shared__ __align__(16) char asm_raw[];
    __half* Qs  = (__half*)asm_raw;            // [64][72]
    __half* Ks  = Qs + 64 * AQS;               // [64][72]
    __half* Vb  = Ks + 64 * AQS;               // [2][64][72]
    __half* Php = Vb + 2 * 64 * AQS;           // [64][72]
    float*  Sf  = (float*)(Php + 64 * AQS);    // [64][68]
    float*  esm = Sf + 64 * SFS;               // [64]
    float*  lsm = esm + 64;                    // [64]

    const int qt   = blockIdx.x;
    const int h    = blockIdx.y;
    const int b    = blockIdx.z;
    const int tid  = threadIdx.x;
    const int lane = tid & 31;
    const int wid  = tid >> 5;
    const int wm   = wid >> 2;      // 0..1
    const int wn   = wid & 3;       // 0..3
    const int lr   = lane >> 2;     // 0..7
    const int lc   = lane & 3;      // 0..3
    const int lane15 = lane & 15;
    const int a_col  = (lane >> 4) << 3;
    const int b_row  = lane & 7;
    const int b_col  = ((lane >> 3) & 1) << 3;

    const size_t base = (size_t)b * TSEQ * QKVN;

    // async 64x64-half tile load (row stride AQS halves)
    auto load_tile = [&](__half* dst, int rowbase, int colbase) {
#pragma unroll
        for (int u = 0; u < 2; ++u) {
            int c   = u * 256 + tid;        // 0..511 chunks of 16B (8 halves)
            int row = c >> 3;
            int col = (c & 7) << 3;
            uint32_t d = smem_u32(dst + row * AQS + col);
            const __half* s = g_qkvh + base + (size_t)(rowbase + row) * QKVN + colbase + col;
            asm volatile("cp.async.cg.shared.global [%0], [%1], 16;" :: "r"(d), "l"(s));
        }
        asm volatile("cp.async.commit_group;" ::: "memory");
    };

    // prologue: group0 = Q + K(0); group1 = V(0)
#pragma unroll
    for (int u = 0; u < 2; ++u) {
        int c   = u * 256 + tid;
        int row = c >> 3;
        int col = (c & 7) << 3;
        uint32_t d = smem_u32(Qs + row * AQS + col);
        const __half* s = g_qkvh + base + (size_t)(qt * 64 + row) * QKVN + h * DHEAD + col;
        asm volatile("cp.async.cg.shared.global [%0], [%1], 16;" :: "r"(d), "l"(s));
    }
    load_tile(Ks, 0, DMODEL + h * DHEAD);          // commits Q+K0
    load_tile(Vb, 0, 2 * DMODEL + h * DHEAD);      // commits V0

    float m_i = -INFINITY, l_i = 0.f;
    float o[2][2][4];
#pragma unroll
    for (int mi = 0; mi < 2; ++mi)
#pragma unroll
        for (int ni = 0; ni < 2; ++ni)
#pragma unroll
            for (int r = 0; r < 4; ++r) o[mi][ni][r] = 0.f;

    for (int kt = 0; kt < NKT; ++kt) {
        asm volatile("cp.async.wait_group 1;" ::: "memory");  // K(kt) (+Q) ready
        __syncthreads();

        // ---- S = Q * K^T : 64x64, k = 64 (4 x k16) ----
        float sfr[2][2][4];
#pragma unroll
        for (int mi = 0; mi < 2; ++mi)
#pragma unroll
            for (int ni = 0; ni < 2; ++ni)
#pragma unroll
                for (int r = 0; r < 4; ++r) sfr[mi][ni][r] = 0.f;

#pragma unroll
        for (int k0 = 0; k0 < DHEAD; k0 += 16) {
            uint32_t af[2][4], bf[2][2];
#pragma unroll
            for (int mi = 0; mi < 2; ++mi)
                ldsm_x4(af[mi], smem_u32(Qs + (wm * 32 + mi * 16 + lane15) * AQS
                                            + k0 + a_col));
#pragma unroll
            for (int ni = 0; ni < 2; ++ni)
                ldsm_x2(bf[ni], smem_u32(Ks + (wn * 16 + ni * 8 + b_row) * AQS
                                            + k0 + b_col));
#pragma unroll
            for (int mi = 0; mi < 2; ++mi)
#pragma unroll
                for (int ni = 0; ni < 2; ++ni)
                    mma_f16(sfr[mi][ni], af[mi], bf[ni]);
        }

        // ---- stage S -> Sf (f32) ----
#pragma unroll
        for (int mi = 0; mi < 2; ++mi)
#pragma unroll
            for (int ni = 0; ni < 2; ++ni) {
                const int r0 = wm * 32 + mi * 16 + lr;
                const int c0 = wn * 16 + ni * 8 + lc * 2;
                *(float2*)&Sf[r0 * SFS + c0] =
                    make_float2(sfr[mi][ni][0], sfr[mi][ni][1]);
                *(float2*)&Sf[(r0 + 8) * SFS + c0] =
                    make_float2(sfr[mi][ni][2], sfr[mi][ni][3]);
            }
        __syncthreads();  // Sf visible; Ks free

        if (kt + 1 < NKT)
            load_tile(Ks, (kt + 1) * 64, DMODEL + h * DHEAD);

        // ---- softmax: row r = tid>>2, 4 threads/row, 16 cols each ----
        {
            const int r  = tid >> 2;
            const int c0 = (tid & 3) * 16;
            float* row = Sf + r * SFS + c0;
            __half* prow = Php + r * AQS + c0;
            float mx = row[0];
#pragma unroll
            for (int j = 1; j < 16; ++j) mx = fmaxf(mx, row[j]);
            mx = fmaxf(mx, __shfl_xor_sync(0xffffffffu, mx, 1));
            mx = fmaxf(mx, __shfl_xor_sync(0xffffffffu, mx, 2));
            float mnew = fmaxf(m_i, mx);
            float e = __expf(0.125f * (m_i - mnew));
            float ls = 0.f;
#pragma unroll
            for (int j = 0; j < 16; ++j) {
                __half ph = __float2half_rn(__expf(0.125f * (row[j] - mnew)));
                prow[j] = ph;
                ls += __half2float(ph);
            }
            ls += __shfl_xor_sync(0xffffffffu, ls, 1);
            ls += __shfl_xor_sync(0xffffffffu, ls, 2);
            l_i = l_i * e + ls;
            m_i = mnew;
            if ((tid & 3) == 0) esm[r] = e;
        }

        if (kt + 1 < NKT)
            asm volatile("cp.async.wait_group 1;" ::: "memory");  // V(kt) ready
        else
            asm volatile("cp.async.wait_group 0;" ::: "memory");
        __syncthreads();  // V(kt) + Php/esm visible

        if (kt + 1 < NKT)
            load_tile(Vb + ((kt + 1) & 1) * 64 * AQS,
                      (kt + 1) * 64, 2 * DMODEL + h * DHEAD);

        // ---- rescale O ----
#pragma unroll
        for (int mi = 0; mi < 2; ++mi) {
            const int r0 = wm * 32 + mi * 16 + lr;
            const float e0 = esm[r0];
            const float e1 = esm[r0 + 8];
#pragma unroll
            for (int ni = 0; ni < 2; ++ni) {
                o[mi][ni][0] *= e0; o[mi][ni][1] *= e0;
                o[mi][ni][2] *= e1; o[mi][ni][3] *= e1;
            }
        }

        // ---- O += P * V : k = 64 (4 x k16); V frags via ldmatrix.trans ----
        const __half* Vs = Vb + (kt & 1) * 64 * AQS;
#pragma unroll
        for (int k0 = 0; k0 < 64; k0 += 16) {
            uint32_t af[2][4], bf[2][2];
#pragma unroll
            for (int mi = 0; mi < 2; ++mi)
                ldsm_x4(af[mi], smem_u32(Php + (wm * 32 + mi * 16 + lane15) * AQS
                                             + k0 + a_col));
#pragma unroll
            for (int ni = 0; ni < 2; ++ni)
                ldsm_x2_t(bf[ni], smem_u32(Vs + (k0 + lane15) * AQS
                                              + wn * 16 + ni * 8));
#pragma unroll
            for (int mi = 0; mi < 2; ++mi)
#pragma unroll
                for (int ni = 0; ni < 2; ++ni)
                    mma_f16(o[mi][ni], af[mi], bf[ni]);
        }
    }

    // ---- epilogue: normalize, convert to fp16, write ----
    if ((tid & 3) == 0) lsm[tid >> 2] = l_i;
    __syncthreads();

#pragma unroll
    for (int mi = 0; mi < 2; ++mi) {
        const int r0 = wm * 32 + mi * 16 + lr;
        const float inv0 = 1.f / lsm[r0];
        const float inv1 = 1.f / lsm[r0 + 8];
#pragma unroll
        for (int ni = 0; ni < 2; ++ni) {
            const int c0 = wn * 16 + ni * 8 + lc * 2;
            __half* p0 = out + ((size_t)b * TSEQ + qt * 64 + r0) * DMODEL + h * DHEAD + c0;
            __half* p1 = out + ((size_t)b * TSEQ + qt * 64 + r0 + 8) * DMODEL + h * DHEAD + c0;
            *(__half2*)p0 = __floats2half2_rn(o[mi][ni][0] * inv0, o[mi][ni][1] * inv0);
            *(__half2*)p1 = __floats2half2_rn(o[mi][ni][2] * inv1, o[mi][ni][3] * inv1);
        }
    }
}

// ---------------------------------------------------------------------------
extern "C" void kernel_launch(void* const* d_in, const int* in_sizes, int n_in,
                              void* d_out, int out_size)
{
    const float* x      = (const float*)d_in[0];   // [2,2048,1024]
    const float* w_qkv  = (const float*)d_in[1];   // [3072,1024]
    const float* w_proj = (const float*)d_in[2];   // [1024,1024]
    float* out = (float*)d_out;                    // [2,2048,1024]

    __half *qkvh, *attnh, *xh, *wqh, *wph;
    cudaGetSymbolAddress((void**)&qkvh,  g_qkvh);
    cudaGetSymbolAddress((void**)&attnh, g_attnh);
    cudaGetSymbolAddress((void**)&xh,    g_xh);
    cudaGetSymbolAddress((void**)&wqh,   g_wqh);
    cudaGetSymbolAddress((void**)&wph,   g_wph);

    cudaFuncSetAttribute(gemm_f16,
                         cudaFuncAttributeMaxDynamicSharedMemorySize, GEMM_SMEM);
    cudaFuncSetAttribute(attn_f16,
                         cudaFuncAttributeMaxDynamicSharedMemorySize, ATTN_SMEM);

    // 0) f32 -> fp16 conversion of all operands (one launch)
    {
        int total = X4 + WQ4 + WP4;
        cvt_all_kernel<<<(total + 255) / 256, 256>>>(x, w_qkv, w_proj);
    }

    // 1) QKV projection -> fp16 qkv
    {
        dim3 g(QKVN / 128, BT / 128);
        gemm_f16<<<g, 256, GEMM_SMEM>>>(xh, wqh, nullptr, qkvh, BT, QKVN, DMODEL);
    }

    // 2) fp16 tensor-core flash attention -> fp16 attn
    {
        dim3 ga(TSEQ / 64, HEADS, NBATCH);
        attn_f16<<<ga, 256, ATTN_SMEM>>>(attnh);
    }

    // 3) Output projection -> fp32 out
    {
        dim3 g(DMODEL / 128, BT / 128);
        gemm_f16<<<g, 256, GEMM_SMEM>>>(attnh, wph, out, nullptr, BT, DMODEL, DMODEL);
    }
}

// round 11
// speedup vs baseline: 6.6710x; 1.4996x over previous
#include <cuda_runtime.h>
#include <cuda_fp16.h>
#include <math.h>
#include <stdint.h>

#define BT     4096      // B*T
#define DMODEL 1024
#define QKVN   3072
#define HEADS  16
#define DHEAD  64
#define TSEQ   2048
#define NBATCH 2
#define NKT    (TSEQ / 64)   // 32 kv tiles

// Scratch (allocation-free rule: __device__ globals)
__device__ __half g_qkvh [(size_t)BT * QKVN];      // fp16 qkv
__device__ __half g_attnh[(size_t)BT * DMODEL];    // fp16 attention out
__device__ __half g_xh   [(size_t)BT * DMODEL];    // fp16 x
__device__ __half g_wqh  [(size_t)QKVN * DMODEL];  // fp16 w_qkv
__device__ __half g_wph  [(size_t)DMODEL * DMODEL];// fp16 w_proj

__device__ __forceinline__ uint32_t smem_u32(const void* p) {
    uint32_t a;
    asm("{ .reg .u64 t; cvta.to.shared.u64 t, %1; cvt.u32.u64 %0, t; }"
        : "=r"(a) : "l"(p));
    return a;
}

// mma.sync m16n8k16 fp16 with fp32 accumulate
__device__ __forceinline__ void mma_f16(float* d, const uint32_t* a, const uint32_t* b) {
    asm volatile(
        "mma.sync.aligned.m16n8k16.row.col.f32.f16.f16.f32 "
        "{%0,%1,%2,%3}, {%4,%5,%6,%7}, {%8,%9}, {%0,%1,%2,%3};"
        : "+f"(d[0]), "+f"(d[1]), "+f"(d[2]), "+f"(d[3])
        : "r"(a[0]), "r"(a[1]), "r"(a[2]), "r"(a[3]), "r"(b[0]), "r"(b[1]));
}

__device__ __forceinline__ void ldsm_x4(uint32_t* r, uint32_t addr) {
    asm volatile("ldmatrix.sync.aligned.m8n8.x4.shared.b16 {%0,%1,%2,%3}, [%4];"
        : "=r"(r[0]), "=r"(r[1]), "=r"(r[2]), "=r"(r[3]) : "r"(addr));
}
__device__ __forceinline__ void ldsm_x2(uint32_t* r, uint32_t addr) {
    asm volatile("ldmatrix.sync.aligned.m8n8.x2.shared.b16 {%0,%1}, [%2];"
        : "=r"(r[0]), "=r"(r[1]) : "r"(addr));
}
__device__ __forceinline__ void ldsm_x2_t(uint32_t* r, uint32_t addr) {
    asm volatile("ldmatrix.sync.aligned.m8n8.x2.trans.shared.b16 {%0,%1}, [%2];"
        : "=r"(r[0]), "=r"(r[1]) : "r"(addr));
}

// ---------------------------------------------------------------------------
// C[M,N] = A[M,K] * B[N,K]^T, fp16 operands, fp32 accum. (proven R10 kernel)
// ---------------------------------------------------------------------------
#define GS   40
#define GSTG (2 * 128 * GS)          // halves per stage (A+B)
#define GEMM_SMEM (4 * GSTG * 2)     // bytes

__global__ __launch_bounds__(256, 2) void gemm_f16(
    const __half* __restrict__ A, const __half* __restrict__ B,
    float* __restrict__ Cf, __half* __restrict__ Ch, int M, int N, int K)
{
    extern __shared__ __half gsm[];

    const int tid  = threadIdx.x;
    const int lane = tid & 31;
    const int wid  = tid >> 5;
    const int wm   = wid >> 2;
    const int wn   = wid & 3;
    const int bn   = blockIdx.x;
    const int bm   = blockIdx.y;
    const int KT   = K >> 5;

    const __half* Ag = A + (size_t)bm * 128 * K;
    const __half* Bg = B + (size_t)bn * 128 * K;

    float acc[4][4][4];
#pragma unroll
    for (int mi = 0; mi < 4; ++mi)
#pragma unroll
        for (int ni = 0; ni < 4; ++ni)
#pragma unroll
            for (int r = 0; r < 4; ++r) acc[mi][ni][r] = 0.f;

    auto fill = [&](int kt) {
        const int st = kt & 3;
        __half* sA = gsm + st * GSTG;
        __half* sB = sA + 128 * GS;
        const int k0 = kt << 5;
#pragma unroll
        for (int u = 0; u < 2; ++u) {
            int f   = u * 256 + tid;
            int row = f >> 2;
            int col = (f & 3) << 3;
            uint32_t da = smem_u32(sA + row * GS + col);
            uint32_t db = smem_u32(sB + row * GS + col);
            const __half* sa = Ag + (size_t)row * K + k0 + col;
            const __half* sb = Bg + (size_t)row * K + k0 + col;
            asm volatile("cp.async.cg.shared.global [%0], [%1], 16;" :: "r"(da), "l"(sa));
            asm volatile("cp.async.cg.shared.global [%0], [%1], 16;" :: "r"(db), "l"(sb));
        }
        asm volatile("cp.async.commit_group;" ::: "memory");
    };

    fill(0); fill(1); fill(2);

    const int lane15 = lane & 15;
    const int a_col  = (lane >> 4) << 3;
    const int b_row  = lane & 7;
    const int b_col  = ((lane >> 3) & 1) << 3;
    const int lr = lane >> 2;
    const int lc = lane & 3;

    for (int kt = 0; kt < KT; ++kt) {
        const int rem = KT - 1 - kt;
        if (rem >= 2)      asm volatile("cp.async.wait_group 2;" ::: "memory");
        else if (rem == 1) asm volatile("cp.async.wait_group 1;" ::: "memory");
        else               asm volatile("cp.async.wait_group 0;" ::: "memory");
        __syncthreads();

        if (kt + 3 < KT) fill(kt + 3);

        const int st = kt & 3;
        const __half* sA = gsm + st * GSTG;
        const __half* sB = sA + 128 * GS;
#pragma unroll
        for (int ks = 0; ks < 2; ++ks) {
            const int k0 = ks << 4;
            uint32_t af[4][4], bf[4][2];
#pragma unroll
            for (int mi = 0; mi < 4; ++mi)
                ldsm_x4(af[mi], smem_u32(sA + (wm * 64 + mi * 16 + lane15) * GS
                                            + k0 + a_col));
#pragma unroll
            for (int ni = 0; ni < 4; ++ni)
                ldsm_x2(bf[ni], smem_u32(sB + (wn * 32 + ni * 8 + b_row) * GS
                                            + k0 + b_col));
#pragma unroll
            for (int mi = 0; mi < 4; ++mi)
#pragma unroll
                for (int ni = 0; ni < 4; ++ni)
                    mma_f16(acc[mi][ni], af[mi], bf[ni]);
        }
    }

#pragma unroll
    for (int mi = 0; mi < 4; ++mi) {
#pragma unroll
        for (int ni = 0; ni < 4; ++ni) {
            const int r0 = bm * 128 + wm * 64 + mi * 16 + lr;
            const int c0 = bn * 128 + wn * 32 + ni * 8 + lc * 2;
            if (Ch) {
                *(__half2*)(Ch + (size_t)r0 * N + c0) =
                    __floats2half2_rn(acc[mi][ni][0], acc[mi][ni][1]);
                *(__half2*)(Ch + (size_t)(r0 + 8) * N + c0) =
                    __floats2half2_rn(acc[mi][ni][2], acc[mi][ni][3]);
            } else {
                *(float2*)(Cf + (size_t)r0 * N + c0) =
                    make_float2(acc[mi][ni][0], acc[mi][ni][1]);
                *(float2*)(Cf + (size_t)(r0 + 8) * N + c0) =
                    make_float2(acc[mi][ni][2], acc[mi][ni][3]);
            }
        }
    }
}

// ---------------------------------------------------------------------------
// Merged f32 -> fp16 conversion of all three operand tensors.
// ---------------------------------------------------------------------------
#define X4  ((BT * DMODEL) / 4)
#define WQ4 ((QKVN * DMODEL) / 4)
#define WP4 ((DMODEL * DMODEL) / 4)

__global__ __launch_bounds__(256) void cvt_all_kernel(
    const float* __restrict__ x, const float* __restrict__ wq,
    const float* __restrict__ wp)
{
    int i = blockIdx.x * blockDim.x + threadIdx.x;
    const float4* src;
    __half2* dst;
    int j;
    if (i < X4)                  { src = (const float4*)x;  dst = (__half2*)g_xh;  j = i; }
    else if (i < X4 + WQ4)       { src = (const float4*)wq; dst = (__half2*)g_wqh; j = i - X4; }
    else if (i < X4 + WQ4 + WP4) { src = (const float4*)wp; dst = (__half2*)g_wph; j = i - X4 - WQ4; }
    else return;
    float4 v = src[j];
    dst[2 * j]     = __floats2half2_rn(v.x, v.y);
    dst[2 * j + 1] = __floats2half2_rn(v.z, v.w);
}

// ---------------------------------------------------------------------------
// FA2-style fp16 flash attention, softmax in registers.
// Block = (b, h, 128-query tile), 8 warps, each warp owns 16 q-rows.
// Per KV tile (64 rows): S (16x64) in register C-frags -> in-register online
// softmax (quad shuffles) -> P repacked to A-frags (no smem) -> O += P*V.
// K/V double-buffered cp.async; ONE __syncthreads + ONE wait per KV tile.
// smem: Q[128][72] + K[2][64][72] + V[2][64][72] halves = 55296 B.
// ---------------------------------------------------------------------------
#define AQS 72
#define ATTN_SMEM ((128 * AQS + 4 * 64 * AQS) * 2)

__global__ __launch_bounds__(256, 2) void attn_f16(__half* __restrict__ out)
{
    extern __shared__ __align__(16) __half ash[];
    __half* Qs = ash;                    // [128][72]
    __half* Kb = Qs + 128 * AQS;         // [2][64][72]
    __half* Vb = Kb + 2 * 64 * AQS;      // [2][64][72]

    const int qt   = blockIdx.x;
    const int h    = blockIdx.y;
    const int b    = blockIdx.z;
    const int tid  = threadIdx.x;
    const int lane = tid & 31;
    const int wid  = tid >> 5;          // warp owns q-rows [wid*16, wid*16+16)
    const int lr   = lane >> 2;         // 0..7
    const int lc   = lane & 3;          // 0..3
    const int lane15 = lane & 15;
    const int a_col  = (lane >> 4) << 3;
    const int b_row  = lane & 7;
    const int b_col  = ((lane >> 3) & 1) << 3;

    const size_t base = (size_t)b * TSEQ * QKVN;

    // K(kt)+V(kt) into buffer kt&1, one commit group
    auto load_kv = [&](int kt) {
        __half* kd = Kb + (kt & 1) * 64 * AQS;
        __half* vd = Vb + (kt & 1) * 64 * AQS;
        const size_t krow = base + (size_t)(kt * 64) * QKVN + DMODEL + h * DHEAD;
        const size_t vrow = base + (size_t)(kt * 64) * QKVN + 2 * DMODEL + h * DHEAD;
#pragma unroll
        for (int u = 0; u < 2; ++u) {
            int c   = u * 256 + tid;      // 0..511 chunks of 16B
            int row = c >> 3;
            int col = (c & 7) << 3;
            uint32_t dk = smem_u32(kd + row * AQS + col);
            uint32_t dv = smem_u32(vd + row * AQS + col);
            const __half* sk = g_qkvh + krow + (size_t)row * QKVN + col;
            const __half* sv = g_qkvh + vrow + (size_t)row * QKVN + col;
            asm volatile("cp.async.cg.shared.global [%0], [%1], 16;" :: "r"(dk), "l"(sk));
            asm volatile("cp.async.cg.shared.global [%0], [%1], 16;" :: "r"(dv), "l"(sv));
        }
        asm volatile("cp.async.commit_group;" ::: "memory");
    };

    // prologue: Q tile (128x64) + K0/V0
#pragma unroll
    for (int u = 0; u < 4; ++u) {
        int c   = u * 256 + tid;          // 0..1023 chunks of 16B
        int row = c >> 3;
        int col = (c & 7) << 3;
        uint32_t d = smem_u32(Qs + row * AQS + col);
        const __half* s = g_qkvh + base + (size_t)(qt * 128 + row) * QKVN + h * DHEAD + col;
        asm volatile("cp.async.cg.shared.global [%0], [%1], 16;" :: "r"(d), "l"(s));
    }
    asm volatile("cp.async.commit_group;" ::: "memory");
    load_kv(0);
    asm volatile("cp.async.wait_group 0;" ::: "memory");
    __syncthreads();

    // hoist Q fragments to registers (Qs never overwritten afterwards)
    uint32_t qf[4][4];
#pragma unroll
    for (int kc = 0; kc < 4; ++kc)
        ldsm_x4(qf[kc], smem_u32(Qs + (wid * 16 + lane15) * AQS + kc * 16 + a_col));

    float m0 = -INFINITY, m1 = -INFINITY, l0 = 0.f, l1 = 0.f;
    float o[8][4];
#pragma unroll
    for (int nb = 0; nb < 8; ++nb)
#pragma unroll
        for (int r = 0; r < 4; ++r) o[nb][r] = 0.f;

    for (int kt = 0; kt < NKT; ++kt) {
        if (kt + 1 < NKT) load_kv(kt + 1);   // overlap with this tile's compute

        const __half* Ks = Kb + (kt & 1) * 64 * AQS;
        const __half* Vs = Vb + (kt & 1) * 64 * AQS;

        // ---- S = Q * K^T : 16x64 per warp, in register C-frags ----
        float s[8][4];
#pragma unroll
        for (int nb = 0; nb < 8; ++nb)
#pragma unroll
            for (int r = 0; r < 4; ++r) s[nb][r] = 0.f;

#pragma unroll
        for (int kc = 0; kc < 4; ++kc) {
            uint32_t bf[8][2];
#pragma unroll
            for (int nb = 0; nb < 8; ++nb)
                ldsm_x2(bf[nb], smem_u32(Ks + (nb * 8 + b_row) * AQS
                                            + kc * 16 + b_col));
#pragma unroll
            for (int nb = 0; nb < 8; ++nb)
                mma_f16(s[nb], qf[kc], bf[nb]);
        }

        // ---- online softmax in registers (rows lr and lr+8) ----
        float mx0 = s[0][0], mx1 = s[0][2];
#pragma unroll
        for (int nb = 0; nb < 8; ++nb) {
            mx0 = fmaxf(mx0, fmaxf(s[nb][0], s[nb][1]));
            mx1 = fmaxf(mx1, fmaxf(s[nb][2], s[nb][3]));
        }
        mx0 = fmaxf(mx0, __shfl_xor_sync(0xffffffffu, mx0, 1));
        mx0 = fmaxf(mx0, __shfl_xor_sync(0xffffffffu, mx0, 2));
        mx1 = fmaxf(mx1, __shfl_xor_sync(0xffffffffu, mx1, 1));
        mx1 = fmaxf(mx1, __shfl_xor_sync(0xffffffffu, mx1, 2));

        const float mn0 = fmaxf(m0, mx0);
        const float mn1 = fmaxf(m1, mx1);
        const float e0 = __expf(0.125f * (m0 - mn0));
        const float e1 = __expf(0.125f * (m1 - mn1));
        m0 = mn0; m1 = mn1;

        // P = exp(S), packed directly into PV A-fragments
        uint32_t pf[4][4];
        float ls0 = 0.f, ls1 = 0.f;
#pragma unroll
        for (int kc = 0; kc < 4; ++kc) {
#pragma unroll
            for (int half_id = 0; half_id < 2; ++half_id) {
                const int nb = 2 * kc + half_id;
                float p00 = __expf(0.125f * (s[nb][0] - mn0));
                float p01 = __expf(0.125f * (s[nb][1] - mn0));
                float p10 = __expf(0.125f * (s[nb][2] - mn1));
                float p11 = __expf(0.125f * (s[nb][3] - mn1));
                __half2 h0 = __floats2half2_rn(p00, p01);
                __half2 h1 = __floats2half2_rn(p10, p11);
                // sum the ROUNDED values so l matches the PV operand exactly
                ls0 += __low2float(h0) + __high2float(h0);
                ls1 += __low2float(h1) + __high2float(h1);
                pf[kc][half_id * 2]     = *(uint32_t*)&h0;   // a0 / a2
                pf[kc][half_id * 2 + 1] = *(uint32_t*)&h1;   // a1 / a3
            }
        }
        ls0 += __shfl_xor_sync(0xffffffffu, ls0, 1);
        ls0 += __shfl_xor_sync(0xffffffffu, ls0, 2);
        ls1 += __shfl_xor_sync(0xffffffffu, ls1, 1);
        ls1 += __shfl_xor_sync(0xffffffffu, ls1, 2);
        l0 = l0 * e0 + ls0;
        l1 = l1 * e1 + ls1;

        // ---- rescale O ----
#pragma unroll
        for (int nb = 0; nb < 8; ++nb) {
            o[nb][0] *= e0; o[nb][1] *= e0;
            o[nb][2] *= e1; o[nb][3] *= e1;
        }

        // ---- O += P * V (V frags via ldmatrix.trans) ----
#pragma unroll
        for (int kc = 0; kc < 4; ++kc) {
            uint32_t bv[8][2];
#pragma unroll
            for (int nb = 0; nb < 8; ++nb)
                ldsm_x2_t(bv[nb], smem_u32(Vs + (kc * 16 + lane15) * AQS + nb * 8));
#pragma unroll
            for (int nb = 0; nb < 8; ++nb)
                mma_f16(o[nb], pf[kc], bv[nb]);
        }

        if (kt + 1 < NKT) {
            asm volatile("cp.async.wait_group 0;" ::: "memory");  // next K/V ready
            __syncthreads();  // all warps done with current buffers
        }
    }

    // ---- epilogue: normalize, write fp16 ----
    const float inv0 = 1.f / l0;
    const float inv1 = 1.f / l1;
    const size_t r0 = (size_t)b * TSEQ + qt * 128 + wid * 16 + lr;
#pragma unroll
    for (int nb = 0; nb < 8; ++nb) {
        const int c0 = h * DHEAD + nb * 8 + lc * 2;
        *(__half2*)(out + r0 * DMODEL + c0) =
            __floats2half2_rn(o[nb][0] * inv0, o[nb][1] * inv0);
        *(__half2*)(out + (r0 + 8) * DMODEL + c0) =
            __floats2half2_rn(o[nb][2] * inv1, o[nb][3] * inv1);
    }
}

// ---------------------------------------------------------------------------
extern "C" void kernel_launch(void* const* d_in, const int* in_sizes, int n_in,
                              void* d_out, int out_size)
{
    const float* x      = (const float*)d_in[0];   // [2,2048,1024]
    const float* w_qkv  = (const float*)d_in[1];   // [3072,1024]
    const float* w_proj = (const float*)d_in[2];   // [1024,1024]
    float* out = (float*)d_out;                    // [2,2048,1024]

    __half *qkvh, *attnh, *xh, *wqh, *wph;
    cudaGetSymbolAddress((void**)&qkvh,  g_qkvh);
    cudaGetSymbolAddress((void**)&attnh, g_attnh);
    cudaGetSymbolAddress((void**)&xh,    g_xh);
    cudaGetSymbolAddress((void**)&wqh,   g_wqh);
    cudaGetSymbolAddress((void**)&wph,   g_wph);

    cudaFuncSetAttribute(gemm_f16,
                         cudaFuncAttributeMaxDynamicSharedMemorySize, GEMM_SMEM);
    cudaFuncSetAttribute(attn_f16,
                         cudaFuncAttributeMaxDynamicSharedMemorySize, ATTN_SMEM);

    // 0) f32 -> fp16 conversion of all operands (one launch)
    {
        int total = X4 + WQ4 + WP4;
        cvt_all_kernel<<<(total + 255) / 256, 256>>>(x, w_qkv, w_proj);
    }

    // 1) QKV projection -> fp16 qkv
    {
        dim3 g(QKVN / 128, BT / 128);
        gemm_f16<<<g, 256, GEMM_SMEM>>>(xh, wqh, nullptr, qkvh, BT, QKVN, DMODEL);
    }

    // 2) FA2-style fp16 flash attention -> fp16 attn
    {
        dim3 ga(TSEQ / 128, HEADS, NBATCH);
        attn_f16<<<ga, 256, ATTN_SMEM>>>(attnh);
    }

    // 3) Output projection -> fp32 out
    {
        dim3 g(DMODEL / 128, BT / 128);
        gemm_f16<<<g, 256, GEMM_SMEM>>>(attnh, wph, out, nullptr, BT, DMODEL, DMODEL);
    }
}